// round 1
// baseline (speedup 1.0000x reference)
#include <cuda_runtime.h>
#include <cstdint>

#define BB 4
#define TT 32
#define SS 1024
#define HH 512
#define H2 1024
#define H3 1536

// Scratch (allocation-free: __device__ globals)
__device__ float g_qf[BB * TT * H2];          // 512 KB
__device__ float g_sf[(size_t)BB * SS * H2];  // 16 MB
__device__ float g_attn[BB * TT * SS];        // 512 KB

__device__ __forceinline__ float tanh_fast(float x) {
    float y;
    asm("tanh.approx.f32 %0, %1;" : "=f"(y) : "f"(x));
    return y;
}

// ---------------------------------------------------------------------------
// K1: qf[b,t,:] = query[b,t,:] @ Wq + bq        (128 x 1024, K=512)
// grid (jchunk=4, tgroup=4, b=4), 256 threads; 8 t-rows per block.
// ---------------------------------------------------------------------------
__global__ __launch_bounds__(256) void qf_kernel(const float* __restrict__ query,
                                                 const float* __restrict__ Wq,
                                                 const float* __restrict__ bq) {
    int jc = blockIdx.x, tg = blockIdx.y, b = blockIdx.z;
    int j = jc * 256 + threadIdx.x;
    int t0 = tg * 8;
    __shared__ float q_s[8][HH];  // 16 KB
    for (int i = threadIdx.x; i < 8 * HH; i += 256) {
        int r = i >> 9, c = i & (HH - 1);
        q_s[r][c] = query[(size_t)(b * TT + t0 + r) * HH + c];
    }
    __syncthreads();
    float acc[8];
    float bias = bq[j];
#pragma unroll
    for (int i = 0; i < 8; i++) acc[i] = bias;
#pragma unroll 4
    for (int k = 0; k < HH; k++) {
        float w = Wq[(size_t)k * H2 + j];
#pragma unroll
        for (int i = 0; i < 8; i++) acc[i] = fmaf(q_s[i][k], w, acc[i]);
    }
#pragma unroll
    for (int i = 0; i < 8; i++)
        g_qf[(size_t)(b * TT + t0 + i) * H2 + j] = acc[i];
}

// ---------------------------------------------------------------------------
// K2: sf = states @ Ws   (M=4096, N=1024, K=1024) classic 128x128x8 SGEMM,
// 256 threads, 8x8 per thread. Writes g_sf.
// ---------------------------------------------------------------------------
__global__ __launch_bounds__(256) void sf_sgemm(const float* __restrict__ A,
                                                const float* __restrict__ Bm) {
    const int M = BB * SS, N = H2, K = H2;
    __shared__ float As[8][128];
    __shared__ float Bs[8][128];
    int tid = threadIdx.x;
    int tx = tid & 15, ty = tid >> 4;
    const float* Ab = A + (size_t)blockIdx.y * 128 * K;
    const float* Bb = Bm + blockIdx.x * 128;
    float Cr[8][8] = {};
    int arow = tid >> 1, acol = (tid & 1) << 2;
    int brow = tid >> 5, bcol = (tid & 31) << 2;
    for (int k0 = 0; k0 < K; k0 += 8) {
        float4 av = *(const float4*)(Ab + (size_t)arow * K + k0 + acol);
        As[acol + 0][arow] = av.x;
        As[acol + 1][arow] = av.y;
        As[acol + 2][arow] = av.z;
        As[acol + 3][arow] = av.w;
        float4 bv = *(const float4*)(Bb + (size_t)(k0 + brow) * N + bcol);
        *(float4*)&Bs[brow][bcol] = bv;
        __syncthreads();
#pragma unroll
        for (int k = 0; k < 8; k++) {
            float a[8], bb[8];
            *(float4*)&a[0] = *(float4*)&As[k][ty * 8];
            *(float4*)&a[4] = *(float4*)&As[k][ty * 8 + 4];
            *(float4*)&bb[0] = *(float4*)&Bs[k][tx * 8];
            *(float4*)&bb[4] = *(float4*)&Bs[k][tx * 8 + 4];
#pragma unroll
            for (int i = 0; i < 8; i++)
#pragma unroll
                for (int j = 0; j < 8; j++)
                    Cr[i][j] = fmaf(a[i], bb[j], Cr[i][j]);
        }
        __syncthreads();
    }
    float* Cb = g_sf + (size_t)(blockIdx.y * 128 + ty * 8) * N + blockIdx.x * 128 + tx * 8;
#pragma unroll
    for (int i = 0; i < 8; i++) {
        *(float4*)(Cb + (size_t)i * N) = *(float4*)&Cr[i][0];
        *(float4*)(Cb + (size_t)i * N + 4) = *(float4*)&Cr[i][4];
    }
}

// ---------------------------------------------------------------------------
// K3: alignments + mask + softmax. One block per (b,t). 256 threads (8 warps).
// Each warp handles s = warp, warp+8, ... Lane owns contiguous d-chunk
// [lane*32, lane*32+32); q and v preloaded into registers so the hot loop is
// LDG + FADD + MUFU.TANH + FFMA only (MUFU-bound by design).
// Writes g_attn[b,t,s] and attentions_t output [b,s,t].
// ---------------------------------------------------------------------------
__global__ __launch_bounds__(256) void attn_kernel(const float* __restrict__ v,
                                                   const int* __restrict__ mask,
                                                   float* __restrict__ out_att) {
    int t = blockIdx.x, b = blockIdx.y;
    int tid = threadIdx.x, lane = tid & 31, warp = tid >> 5;
    __shared__ float al[SS];
    __shared__ float red[8];

    const float* qfrow = g_qf + (size_t)(b * TT + t) * H2 + lane * 32;
    const float* vrow = v + lane * 32;
    float qr[32], vr[32];
#pragma unroll
    for (int u = 0; u < 8; u++) {
        float4 qv = *(const float4*)(qfrow + u * 4);
        float4 vv = *(const float4*)(vrow + u * 4);
        qr[u * 4 + 0] = qv.x; qr[u * 4 + 1] = qv.y;
        qr[u * 4 + 2] = qv.z; qr[u * 4 + 3] = qv.w;
        vr[u * 4 + 0] = vv.x; vr[u * 4 + 1] = vv.y;
        vr[u * 4 + 2] = vv.z; vr[u * 4 + 3] = vv.w;
    }

    for (int s = warp; s < SS; s += 8) {
        const float* sfrow = g_sf + ((size_t)(b * SS + s)) * H2 + lane * 32;
        float acc = 0.f;
#pragma unroll
        for (int u = 0; u < 8; u++) {
            float4 sv = *(const float4*)(sfrow + u * 4);
            acc = fmaf(tanh_fast(qr[u * 4 + 0] + sv.x), vr[u * 4 + 0], acc);
            acc = fmaf(tanh_fast(qr[u * 4 + 1] + sv.y), vr[u * 4 + 1], acc);
            acc = fmaf(tanh_fast(qr[u * 4 + 2] + sv.z), vr[u * 4 + 2], acc);
            acc = fmaf(tanh_fast(qr[u * 4 + 3] + sv.w), vr[u * 4 + 3], acc);
        }
#pragma unroll
        for (int o = 16; o; o >>= 1) acc += __shfl_xor_sync(0xffffffffu, acc, o);
        if (lane == 0) al[s] = mask[b * SS + s] ? acc : -1e30f;
    }
    __syncthreads();

    // softmax over S=1024
    float m = -1e30f;
#pragma unroll
    for (int i = 0; i < 4; i++) m = fmaxf(m, al[tid + i * 256]);
#pragma unroll
    for (int o = 16; o; o >>= 1) m = fmaxf(m, __shfl_xor_sync(0xffffffffu, m, o));
    if (lane == 0) red[warp] = m;
    __syncthreads();
    float mx = -1e30f;
#pragma unroll
    for (int i = 0; i < 8; i++) mx = fmaxf(mx, red[i]);

    float e[4];
    float ssum = 0.f;
#pragma unroll
    for (int i = 0; i < 4; i++) {
        e[i] = __expf(al[tid + i * 256] - mx);
        ssum += e[i];
    }
#pragma unroll
    for (int o = 16; o; o >>= 1) ssum += __shfl_xor_sync(0xffffffffu, ssum, o);
    __syncthreads();  // all reads of red done before reuse
    if (lane == 0) red[warp] = ssum;
    __syncthreads();
    float tot = 0.f;
#pragma unroll
    for (int i = 0; i < 8; i++) tot += red[i];
    float inv = 1.0f / tot;

    float* ga = g_attn + (size_t)(b * TT + t) * SS;
    float* oa = out_att + (size_t)b * SS * TT + t;  // [b][s][t]
#pragma unroll
    for (int i = 0; i < 4; i++) {
        int s = tid + i * 256;
        float w = e[i] * inv;
        ga[s] = w;
        oa[(size_t)s * TT] = w;
    }
}

// ---------------------------------------------------------------------------
// K4: context[b,t,:] = attn[b,t,:] @ states[b]   — t-grouped (8 t / block) so
// states is read only 8x per batch (stays L2-resident).
// grid (dchunk=8, tgroup=4, b=4), 128 threads.
// ---------------------------------------------------------------------------
__global__ __launch_bounds__(128) void ctx_kernel(const float* __restrict__ states,
                                                  float* __restrict__ out_ctx) {
    int dc = blockIdx.x, tg = blockIdx.y, b = blockIdx.z;
    int t0 = tg * 8;
    int d = dc * 128 + threadIdx.x;
    __shared__ float aw[8][SS];  // 32 KB
    for (int i = threadIdx.x; i < 8 * SS; i += 128) {
        int r = i >> 10, c = i & (SS - 1);
        aw[r][c] = g_attn[(size_t)(b * TT + t0 + r) * SS + c];
    }
    __syncthreads();
    float acc[8] = {};
    const float* sb = states + ((size_t)b * SS) * H2 + d;
#pragma unroll 4
    for (int s = 0; s < SS; s++) {
        float sv = sb[(size_t)s * H2];
#pragma unroll
        for (int i = 0; i < 8; i++) acc[i] = fmaf(aw[i][s], sv, acc[i]);
    }
#pragma unroll
    for (int i = 0; i < 8; i++)
        out_ctx[(size_t)(b * TT + t0 + i) * H2 + d] = acc[i];
}

// ---------------------------------------------------------------------------
// K5: attention_hidden = [context, query] @ Wc + bc   (128 x 512, K=1536)
// grid (tgroup=4, b=4), 512 threads, 8 t-rows per block.
// ---------------------------------------------------------------------------
__global__ __launch_bounds__(512) void hidden_kernel(const float* __restrict__ query,
                                                     const float* __restrict__ Wc,
                                                     const float* __restrict__ bc,
                                                     const float* __restrict__ ctx,
                                                     float* __restrict__ out_hid) {
    int tg = blockIdx.x, b = blockIdx.y;
    int t0 = tg * 8;
    int h = threadIdx.x;
    __shared__ float cc[8][H3];  // 48 KB
    for (int i = threadIdx.x; i < 8 * H2; i += 512) {
        int r = i >> 10, c = i & (H2 - 1);
        cc[r][c] = ctx[(size_t)(b * TT + t0 + r) * H2 + c];
    }
    for (int i = threadIdx.x; i < 8 * HH; i += 512) {
        int r = i >> 9, c = i & (HH - 1);
        cc[r][H2 + c] = query[(size_t)(b * TT + t0 + r) * HH + c];
    }
    __syncthreads();
    float acc[8];
    float bias = bc[h];
#pragma unroll
    for (int i = 0; i < 8; i++) acc[i] = bias;
#pragma unroll 2
    for (int k = 0; k < H3; k++) {
        float w = Wc[(size_t)k * HH + h];
#pragma unroll
        for (int i = 0; i < 8; i++) acc[i] = fmaf(cc[i][k], w, acc[i]);
    }
#pragma unroll
    for (int i = 0; i < 8; i++)
        out_hid[(size_t)(b * TT + t0 + i) * HH + h] = acc[i];
}

// ---------------------------------------------------------------------------
extern "C" void kernel_launch(void* const* d_in, const int* in_sizes, int n_in,
                              void* d_out, int out_size) {
    const float* query  = (const float*)d_in[0];
    const float* states = (const float*)d_in[1];
    const int*   mask   = (const int*)d_in[2];
    const float* Wq     = (const float*)d_in[3];
    const float* bq     = (const float*)d_in[4];
    const float* Ws     = (const float*)d_in[5];
    const float* v      = (const float*)d_in[6];
    const float* Wc     = (const float*)d_in[7];
    const float* bc     = (const float*)d_in[8];

    float* out_ctx = (float*)d_out;                  // (B,T,2H) = 131072
    float* out_hid = out_ctx + BB * TT * H2;         // (B,T,H)  = 65536
    float* out_att = out_hid + BB * TT * HH;         // (B,S,T)  = 131072

    qf_kernel<<<dim3(4, 4, 4), 256>>>(query, Wq, bq);
    sf_sgemm<<<dim3(H2 / 128, (BB * SS) / 128), 256>>>(states, Ws);
    attn_kernel<<<dim3(TT, BB), 256>>>(v, mask, out_att);
    ctx_kernel<<<dim3(8, 4, 4), 128>>>(states, out_ctx);
    hidden_kernel<<<dim3(4, 4), 512>>>(query, Wc, bc, out_ctx, out_hid);
}

// round 2
// speedup vs baseline: 1.1890x; 1.1890x over previous
#include <cuda_runtime.h>
#include <cstdint>

#define BB 4
#define TT 32
#define SS 1024
#define HH 512
#define H2 1024
#define H3 1536

typedef unsigned long long ull;

// Scratch (allocation-free: __device__ globals)
__device__ float g_qf[BB * TT * H2];          // 512 KB
__device__ float g_sf[(size_t)BB * SS * H2];  // 16 MB
__device__ float g_attn[BB * TT * SS];        // 512 KB

__device__ __forceinline__ float tanh_fast(float x) {
    float y;
    asm("tanh.approx.f32 %0, %1;" : "=f"(y) : "f"(x));
    return y;
}

__device__ __forceinline__ ull pack_dup(float v) {
    ull r;
    asm("mov.b64 %0, {%1, %1};" : "=l"(r) : "f"(v));
    return r;
}

__device__ __forceinline__ void fma2(ull& c, ull a, ull b) {
    asm("fma.rn.f32x2 %0, %1, %2, %3;" : "=l"(c) : "l"(a), "l"(b), "l"(c));
}

// ---------------------------------------------------------------------------
// K0: zero out_ctx + out_hid (atomicAdd targets). 196608 floats = 49152 float4.
// ---------------------------------------------------------------------------
__global__ __launch_bounds__(256) void zero_kernel(float4* __restrict__ p) {
    int i = blockIdx.x * 1024 + threadIdx.x;
#pragma unroll
    for (int u = 0; u < 4; u++) p[i + u * 256] = make_float4(0.f, 0.f, 0.f, 0.f);
}

// ---------------------------------------------------------------------------
// K1: qf = query @ Wq + bq   (128 x 1024, K=512)
// grid (jc=8, tg=4, b=4) = 128 blocks, 128 threads.
// ---------------------------------------------------------------------------
__global__ __launch_bounds__(128) void qf_kernel(const float* __restrict__ query,
                                                 const float* __restrict__ Wq,
                                                 const float* __restrict__ bq) {
    int jc = blockIdx.x, tg = blockIdx.y, b = blockIdx.z;
    int j = jc * 128 + threadIdx.x;
    int t0 = tg * 8;
    __shared__ float q_s[8][HH];  // 16 KB
    for (int i = threadIdx.x; i < 8 * HH; i += 128) {
        int r = i >> 9, c = i & (HH - 1);
        q_s[r][c] = query[(size_t)(b * TT + t0 + r) * HH + c];
    }
    __syncthreads();
    float acc[8];
    float bias = bq[j];
#pragma unroll
    for (int i = 0; i < 8; i++) acc[i] = bias;
#pragma unroll 8
    for (int k = 0; k < HH; k++) {
        float w = Wq[(size_t)k * H2 + j];
#pragma unroll
        for (int i = 0; i < 8; i++) acc[i] = fmaf(q_s[i][k], w, acc[i]);
    }
#pragma unroll
    for (int i = 0; i < 8; i++)
        g_qf[(size_t)(b * TT + t0 + i) * H2 + j] = acc[i];
}

// ---------------------------------------------------------------------------
// K2: sf = states @ Ws  (M=4096, N=1024, K=1024), 128x128 tile, 256 threads,
// 8x8 per thread computed as 8 x 4 packed-f32x2 via fma.rn.f32x2 (FFMA2).
// A is stored DUPLICATED in smem ({v,v} pairs) so the inner loop has zero
// pack instructions: 8 LDS.64 + 2 LDS.128 + 32 FFMA2 per k.
// ---------------------------------------------------------------------------
#define KSTEP 16
__global__ __launch_bounds__(256) void sf_sgemm(const float* __restrict__ A,
                                                const float* __restrict__ Bm) {
    const int N = H2, K = H2;
    __shared__ ull Asd[KSTEP][128];   // 16 KB: Asd[k][m] = {A[m][k], A[m][k]}
    __shared__ float Bs[KSTEP][128];  // 8 KB
    int tid = threadIdx.x;
    int tx = tid & 15, ty = tid >> 4;
    const float* Ab = A + (size_t)blockIdx.y * 128 * K;
    const float* Bb = Bm + blockIdx.x * 128;

    ull c[8][4];
#pragma unroll
    for (int i = 0; i < 8; i++)
#pragma unroll
        for (int j = 0; j < 4; j++) c[i][j] = 0ull;

    int arow = tid >> 1, acol = (tid & 1) * 8;
    int brow = tid >> 4, bcol = (tid & 15) * 8;

    for (int k0 = 0; k0 < K; k0 += KSTEP) {
        float4 av0 = *(const float4*)(Ab + (size_t)arow * K + k0 + acol);
        float4 av1 = *(const float4*)(Ab + (size_t)arow * K + k0 + acol + 4);
        float4 bv0 = *(const float4*)(Bb + (size_t)(k0 + brow) * N + bcol);
        float4 bv1 = *(const float4*)(Bb + (size_t)(k0 + brow) * N + bcol + 4);
        Asd[acol + 0][arow] = pack_dup(av0.x);
        Asd[acol + 1][arow] = pack_dup(av0.y);
        Asd[acol + 2][arow] = pack_dup(av0.z);
        Asd[acol + 3][arow] = pack_dup(av0.w);
        Asd[acol + 4][arow] = pack_dup(av1.x);
        Asd[acol + 5][arow] = pack_dup(av1.y);
        Asd[acol + 6][arow] = pack_dup(av1.z);
        Asd[acol + 7][arow] = pack_dup(av1.w);
        *(float4*)&Bs[brow][bcol] = bv0;
        *(float4*)&Bs[brow][bcol + 4] = bv1;
        __syncthreads();
#pragma unroll
        for (int k = 0; k < KSTEP; k++) {
            ull a[8];
#pragma unroll
            for (int i = 0; i < 8; i++) a[i] = Asd[k][ty * 8 + i];
            ull b[4];
            float4 bq0 = *(float4*)&Bs[k][tx * 8];
            float4 bq1 = *(float4*)&Bs[k][tx * 8 + 4];
            b[0] = *(ull*)&bq0.x; b[1] = *(ull*)&bq0.z;
            b[2] = *(ull*)&bq1.x; b[3] = *(ull*)&bq1.z;
#pragma unroll
            for (int i = 0; i < 8; i++)
#pragma unroll
                for (int j = 0; j < 4; j++) fma2(c[i][j], a[i], b[j]);
        }
        __syncthreads();
    }
    float* Cb = g_sf + (size_t)(blockIdx.y * 128 + ty * 8) * N + blockIdx.x * 128 + tx * 8;
#pragma unroll
    for (int i = 0; i < 8; i++) {
#pragma unroll
        for (int j = 0; j < 4; j++)
            *(ull*)(Cb + (size_t)i * N + 2 * j) = c[i][j];
    }
}

// ---------------------------------------------------------------------------
// K3: alignments + mask + softmax. One block per (b,t). 256 threads.
// ---------------------------------------------------------------------------
__global__ __launch_bounds__(256) void attn_kernel(const float* __restrict__ v,
                                                   const int* __restrict__ mask,
                                                   float* __restrict__ out_att) {
    int t = blockIdx.x, b = blockIdx.y;
    int tid = threadIdx.x, lane = tid & 31, warp = tid >> 5;
    __shared__ float al[SS];
    __shared__ float red[8];

    const float* qfrow = g_qf + (size_t)(b * TT + t) * H2 + lane * 32;
    const float* vrow = v + lane * 32;
    float qr[32], vr[32];
#pragma unroll
    for (int u = 0; u < 8; u++) {
        float4 qv = *(const float4*)(qfrow + u * 4);
        float4 vv = *(const float4*)(vrow + u * 4);
        qr[u * 4 + 0] = qv.x; qr[u * 4 + 1] = qv.y;
        qr[u * 4 + 2] = qv.z; qr[u * 4 + 3] = qv.w;
        vr[u * 4 + 0] = vv.x; vr[u * 4 + 1] = vv.y;
        vr[u * 4 + 2] = vv.z; vr[u * 4 + 3] = vv.w;
    }

    for (int s = warp; s < SS; s += 8) {
        const float* sfrow = g_sf + ((size_t)(b * SS + s)) * H2 + lane * 32;
        float acc = 0.f;
#pragma unroll
        for (int u = 0; u < 8; u++) {
            float4 sv = *(const float4*)(sfrow + u * 4);
            acc = fmaf(tanh_fast(qr[u * 4 + 0] + sv.x), vr[u * 4 + 0], acc);
            acc = fmaf(tanh_fast(qr[u * 4 + 1] + sv.y), vr[u * 4 + 1], acc);
            acc = fmaf(tanh_fast(qr[u * 4 + 2] + sv.z), vr[u * 4 + 2], acc);
            acc = fmaf(tanh_fast(qr[u * 4 + 3] + sv.w), vr[u * 4 + 3], acc);
        }
#pragma unroll
        for (int o = 16; o; o >>= 1) acc += __shfl_xor_sync(0xffffffffu, acc, o);
        if (lane == 0) al[s] = mask[b * SS + s] ? acc : -1e30f;
    }
    __syncthreads();

    float m = -1e30f;
#pragma unroll
    for (int i = 0; i < 4; i++) m = fmaxf(m, al[tid + i * 256]);
#pragma unroll
    for (int o = 16; o; o >>= 1) m = fmaxf(m, __shfl_xor_sync(0xffffffffu, m, o));
    if (lane == 0) red[warp] = m;
    __syncthreads();
    float mx = -1e30f;
#pragma unroll
    for (int i = 0; i < 8; i++) mx = fmaxf(mx, red[i]);

    float e[4];
    float ssum = 0.f;
#pragma unroll
    for (int i = 0; i < 4; i++) {
        e[i] = __expf(al[tid + i * 256] - mx);
        ssum += e[i];
    }
#pragma unroll
    for (int o = 16; o; o >>= 1) ssum += __shfl_xor_sync(0xffffffffu, ssum, o);
    __syncthreads();
    if (lane == 0) red[warp] = ssum;
    __syncthreads();
    float tot = 0.f;
#pragma unroll
    for (int i = 0; i < 8; i++) tot += red[i];
    float inv = 1.0f / tot;

    float* ga = g_attn + (size_t)(b * TT + t) * SS;
    float* oa = out_att + (size_t)b * SS * TT + t;
#pragma unroll
    for (int i = 0; i < 4; i++) {
        int s = tid + i * 256;
        float w = e[i] * inv;
        ga[s] = w;
        oa[(size_t)s * TT] = w;
    }
}

// ---------------------------------------------------------------------------
// K4: context = attn @ states, split-S with atomicAdd epilogue.
// grid (dc=8, sc=8, b=4) = 256 blocks, 128 threads. Each thread owns column d,
// accumulates all 32 t-rows in registers over a 128-s slice.
// ---------------------------------------------------------------------------
__global__ __launch_bounds__(128) void ctx_kernel(const float* __restrict__ states,
                                                  float* __restrict__ out_ctx) {
    int dc = blockIdx.x, sc = blockIdx.y, b = blockIdx.z;
    int d = dc * 128 + threadIdx.x;
    int s0 = sc * 128;
    __shared__ float aw[TT][128];  // 16 KB
    for (int i = threadIdx.x; i < TT * 128; i += 128) {
        int t = i >> 7, sl = i & 127;
        aw[t][sl] = g_attn[(size_t)(b * TT + t) * SS + s0 + sl];
    }
    __syncthreads();
    float acc[TT] = {};
    const float* sb = states + ((size_t)b * SS + s0) * H2 + d;
#pragma unroll 2
    for (int sl = 0; sl < 128; sl++) {
        float sv = sb[(size_t)sl * H2];
#pragma unroll
        for (int t = 0; t < TT; t++) acc[t] = fmaf(aw[t][sl], sv, acc[t]);
    }
#pragma unroll
    for (int t = 0; t < TT; t++)
        atomicAdd(&out_ctx[(size_t)(b * TT + t) * H2 + d], acc[t]);
}

// ---------------------------------------------------------------------------
// K5: attention_hidden = [context, query] @ Wc + bc, split-K with atomics.
// grid (hc=4, tg=4, b*4+kc=16) = 256 blocks, 128 threads. K-range 384/block.
// ---------------------------------------------------------------------------
__global__ __launch_bounds__(128) void hidden_kernel(const float* __restrict__ query,
                                                     const float* __restrict__ Wc,
                                                     const float* __restrict__ bc,
                                                     const float* __restrict__ ctx,
                                                     float* __restrict__ out_hid) {
    int hc = blockIdx.x, tg = blockIdx.y;
    int b = blockIdx.z >> 2, kc = blockIdx.z & 3;
    int h = hc * 128 + threadIdx.x;
    int t0 = tg * 8, k0 = kc * 384;
    __shared__ float cc[8][384];  // 12 KB
    for (int i = threadIdx.x; i < 8 * 384; i += 128) {
        int r = i / 384, col = i - r * 384;
        int gk = k0 + col;
        cc[r][col] = (gk < H2)
                         ? ctx[(size_t)(b * TT + t0 + r) * H2 + gk]
                         : query[(size_t)(b * TT + t0 + r) * HH + gk - H2];
    }
    __syncthreads();
    float acc[8];
    float bias = (kc == 0) ? bc[h] : 0.f;
#pragma unroll
    for (int i = 0; i < 8; i++) acc[i] = bias;
#pragma unroll 4
    for (int k = 0; k < 384; k++) {
        float w = Wc[(size_t)(k0 + k) * HH + h];
#pragma unroll
        for (int i = 0; i < 8; i++) acc[i] = fmaf(cc[i][k], w, acc[i]);
    }
#pragma unroll
    for (int i = 0; i < 8; i++)
        atomicAdd(&out_hid[(size_t)(b * TT + t0 + i) * HH + h], acc[i]);
}

// ---------------------------------------------------------------------------
extern "C" void kernel_launch(void* const* d_in, const int* in_sizes, int n_in,
                              void* d_out, int out_size) {
    const float* query  = (const float*)d_in[0];
    const float* states = (const float*)d_in[1];
    const int*   mask   = (const int*)d_in[2];
    const float* Wq     = (const float*)d_in[3];
    const float* bq     = (const float*)d_in[4];
    const float* Ws     = (const float*)d_in[5];
    const float* v      = (const float*)d_in[6];
    const float* Wc     = (const float*)d_in[7];
    const float* bc     = (const float*)d_in[8];

    float* out_ctx = (float*)d_out;                  // (B,T,2H) = 131072
    float* out_hid = out_ctx + BB * TT * H2;         // (B,T,H)  = 65536
    float* out_att = out_hid + BB * TT * HH;         // (B,S,T)  = 131072

    zero_kernel<<<48, 256>>>((float4*)d_out);        // zero ctx+hid (196608 floats)
    qf_kernel<<<dim3(8, 4, 4), 128>>>(query, Wq, bq);
    sf_sgemm<<<dim3(H2 / 128, (BB * SS) / 128), 256>>>(states, Ws);
    attn_kernel<<<dim3(TT, BB), 256>>>(v, mask, out_att);
    ctx_kernel<<<dim3(8, 8, 4), 128>>>(states, out_ctx);
    hidden_kernel<<<dim3(4, 4, 16), 128>>>(query, Wc, bc, out_ctx, out_hid);
}

// round 3
// speedup vs baseline: 1.2945x; 1.0887x over previous
#include <cuda_runtime.h>
#include <cstdint>

#define BB 4
#define TT 32
#define SS 1024
#define HH 512
#define H2 1024
#define H3 1536

typedef unsigned long long ull;

// Scratch (allocation-free: __device__ globals)
__device__ float g_qf[BB * TT * H2];          // 512 KB
__device__ float g_sf[(size_t)BB * SS * H2];  // 16 MB
__device__ float g_attn[BB * TT * SS];        // 512 KB (raw alignments, then softmaxed in place)

__device__ __forceinline__ float tanh_fast(float x) {
    float y;
    asm("tanh.approx.f32 %0, %1;" : "=f"(y) : "f"(x));
    return y;
}

__device__ __forceinline__ ull pack_dup(float v) {
    ull r;
    asm("mov.b64 %0, {%1, %1};" : "=l"(r) : "f"(v));
    return r;
}

__device__ __forceinline__ void fma2(ull& c, ull a, ull b) {
    asm("fma.rn.f32x2 %0, %1, %2, %3;" : "=l"(c) : "l"(a), "l"(b), "l"(c));
}

// ---------------------------------------------------------------------------
// K0: zero out_ctx + out_hid (atomicAdd targets).
// ---------------------------------------------------------------------------
__global__ __launch_bounds__(256) void zero_kernel(float4* __restrict__ p) {
    int i = blockIdx.x * 1024 + threadIdx.x;
#pragma unroll
    for (int u = 0; u < 4; u++) p[i + u * 256] = make_float4(0.f, 0.f, 0.f, 0.f);
}

// ---------------------------------------------------------------------------
// K1: qf = query @ Wq + bq   (128 x 1024, K=512)
// ---------------------------------------------------------------------------
__global__ __launch_bounds__(128) void qf_kernel(const float* __restrict__ query,
                                                 const float* __restrict__ Wq,
                                                 const float* __restrict__ bq) {
    int jc = blockIdx.x, tg = blockIdx.y, b = blockIdx.z;
    int j = jc * 128 + threadIdx.x;
    int t0 = tg * 8;
    __shared__ float q_s[8][HH];
    for (int i = threadIdx.x; i < 8 * HH; i += 128) {
        int r = i >> 9, c = i & (HH - 1);
        q_s[r][c] = query[(size_t)(b * TT + t0 + r) * HH + c];
    }
    __syncthreads();
    float acc[8];
    float bias = bq[j];
#pragma unroll
    for (int i = 0; i < 8; i++) acc[i] = bias;
#pragma unroll 8
    for (int k = 0; k < HH; k++) {
        float w = Wq[(size_t)k * H2 + j];
#pragma unroll
        for (int i = 0; i < 8; i++) acc[i] = fmaf(q_s[i][k], w, acc[i]);
    }
#pragma unroll
    for (int i = 0; i < 8; i++)
        g_qf[(size_t)(b * TT + t0 + i) * H2 + j] = acc[i];
}

// ---------------------------------------------------------------------------
// K2: sf = states @ Ws  (M=4096, N=1024, K=1024). 128x128 tile, 256 threads,
// FFMA2 inner loop, register double-buffered global loads.
// ---------------------------------------------------------------------------
#define KSTEP 16
__global__ __launch_bounds__(256) void sf_sgemm(const float* __restrict__ A,
                                                const float* __restrict__ Bm) {
    const int N = H2, K = H2;
    __shared__ ull Asd[KSTEP][128];   // 16 KB
    __shared__ float Bs[KSTEP][128];  // 8 KB
    int tid = threadIdx.x;
    int tx = tid & 15, ty = tid >> 4;
    const float* Ab = A + (size_t)blockIdx.y * 128 * K;
    const float* Bb = Bm + blockIdx.x * 128;

    ull c[8][4];
#pragma unroll
    for (int i = 0; i < 8; i++)
#pragma unroll
        for (int j = 0; j < 4; j++) c[i][j] = 0ull;

    int arow = tid >> 1, acol = (tid & 1) * 8;
    int brow = tid >> 4, bcol = (tid & 15) * 8;

    const float* Aptr = Ab + (size_t)arow * K + acol;
    const float* Bptr = Bb + (size_t)brow * N + bcol;

    float4 av0 = *(const float4*)(Aptr);
    float4 av1 = *(const float4*)(Aptr + 4);
    float4 bv0 = *(const float4*)(Bptr);
    float4 bv1 = *(const float4*)(Bptr + 4);

    for (int k0 = 0; k0 < K; k0 += KSTEP) {
        Asd[acol + 0][arow] = pack_dup(av0.x);
        Asd[acol + 1][arow] = pack_dup(av0.y);
        Asd[acol + 2][arow] = pack_dup(av0.z);
        Asd[acol + 3][arow] = pack_dup(av0.w);
        Asd[acol + 4][arow] = pack_dup(av1.x);
        Asd[acol + 5][arow] = pack_dup(av1.y);
        Asd[acol + 6][arow] = pack_dup(av1.z);
        Asd[acol + 7][arow] = pack_dup(av1.w);
        *(float4*)&Bs[brow][bcol] = bv0;
        *(float4*)&Bs[brow][bcol + 4] = bv1;
        __syncthreads();
        if (k0 + KSTEP < K) {  // prefetch next tile while computing
            av0 = *(const float4*)(Aptr + k0 + KSTEP);
            av1 = *(const float4*)(Aptr + k0 + KSTEP + 4);
            bv0 = *(const float4*)(Bptr + (size_t)(k0 + KSTEP) * N);
            bv1 = *(const float4*)(Bptr + (size_t)(k0 + KSTEP) * N + 4);
        }
#pragma unroll
        for (int k = 0; k < KSTEP; k++) {
            ull a[8];
#pragma unroll
            for (int i = 0; i < 8; i++) a[i] = Asd[k][ty * 8 + i];
            ull b[4];
            float4 bq0 = *(float4*)&Bs[k][tx * 8];
            float4 bq1 = *(float4*)&Bs[k][tx * 8 + 4];
            b[0] = *(ull*)&bq0.x; b[1] = *(ull*)&bq0.z;
            b[2] = *(ull*)&bq1.x; b[3] = *(ull*)&bq1.z;
#pragma unroll
            for (int i = 0; i < 8; i++)
#pragma unroll
                for (int j = 0; j < 4; j++) fma2(c[i][j], a[i], b[j]);
        }
        __syncthreads();
    }
    float* Cb = g_sf + (size_t)(blockIdx.y * 128 + ty * 8) * N + blockIdx.x * 128 + tx * 8;
#pragma unroll
    for (int i = 0; i < 8; i++) {
#pragma unroll
        for (int j = 0; j < 4; j++)
            *(ull*)(Cb + (size_t)i * N + 2 * j) = c[i][j];
    }
}

// ---------------------------------------------------------------------------
// K3a: raw alignments. grid (schunk=8, t=32, b=4) = 1024 blocks, 256 thr.
// Block covers s in [s0, s0+128). Warp handles s = s0+warp+8i (16 rows).
// Lane owns contiguous d-chunk [lane*32, +32); q,v preloaded in registers.
// 4 accumulators break the FFMA chain. Writes masked raw alignment.
// ---------------------------------------------------------------------------
__global__ __launch_bounds__(256) void align_kernel(const float* __restrict__ v,
                                                    const int* __restrict__ mask) {
    int sc = blockIdx.x, t = blockIdx.y, b = blockIdx.z;
    int s0 = sc * 128;
    int tid = threadIdx.x, lane = tid & 31, warp = tid >> 5;

    const float* qfrow = g_qf + (size_t)(b * TT + t) * H2 + lane * 32;
    const float* vrow = v + lane * 32;
    float qr[32], vr[32];
#pragma unroll
    for (int u = 0; u < 8; u++) {
        float4 qv = *(const float4*)(qfrow + u * 4);
        float4 vv = *(const float4*)(vrow + u * 4);
        qr[u * 4 + 0] = qv.x; qr[u * 4 + 1] = qv.y;
        qr[u * 4 + 2] = qv.z; qr[u * 4 + 3] = qv.w;
        vr[u * 4 + 0] = vv.x; vr[u * 4 + 1] = vv.y;
        vr[u * 4 + 2] = vv.z; vr[u * 4 + 3] = vv.w;
    }

    float* ga = g_attn + (size_t)(b * TT + t) * SS;
#pragma unroll 1
    for (int i = 0; i < 16; i++) {
        int s = s0 + warp + i * 8;
        const float* sfrow = g_sf + ((size_t)(b * SS + s)) * H2 + lane * 32;
        float a0 = 0.f, a1 = 0.f, a2 = 0.f, a3 = 0.f;
#pragma unroll
        for (int u = 0; u < 8; u++) {
            float4 sv = *(const float4*)(sfrow + u * 4);
            a0 = fmaf(tanh_fast(qr[u * 4 + 0] + sv.x), vr[u * 4 + 0], a0);
            a1 = fmaf(tanh_fast(qr[u * 4 + 1] + sv.y), vr[u * 4 + 1], a1);
            a2 = fmaf(tanh_fast(qr[u * 4 + 2] + sv.z), vr[u * 4 + 2], a2);
            a3 = fmaf(tanh_fast(qr[u * 4 + 3] + sv.w), vr[u * 4 + 3], a3);
        }
        float acc = (a0 + a1) + (a2 + a3);
#pragma unroll
        for (int o = 16; o; o >>= 1) acc += __shfl_xor_sync(0xffffffffu, acc, o);
        if (lane == 0) ga[s] = mask[b * SS + s] ? acc : -1e30f;
    }
}

// ---------------------------------------------------------------------------
// K3b: softmax over S=1024 per (b,t); writes g_attn (in place) + out_att.
// ---------------------------------------------------------------------------
__global__ __launch_bounds__(256) void softmax_kernel(float* __restrict__ out_att) {
    int t = blockIdx.x, b = blockIdx.y;
    int tid = threadIdx.x, lane = tid & 31, warp = tid >> 5;
    __shared__ float red[8];

    float* ga = g_attn + (size_t)(b * TT + t) * SS;
    float al[4];
#pragma unroll
    for (int i = 0; i < 4; i++) al[i] = ga[tid + i * 256];

    float m = fmaxf(fmaxf(al[0], al[1]), fmaxf(al[2], al[3]));
#pragma unroll
    for (int o = 16; o; o >>= 1) m = fmaxf(m, __shfl_xor_sync(0xffffffffu, m, o));
    if (lane == 0) red[warp] = m;
    __syncthreads();
    float mx = -1e30f;
#pragma unroll
    for (int i = 0; i < 8; i++) mx = fmaxf(mx, red[i]);

    float e[4];
    float ssum = 0.f;
#pragma unroll
    for (int i = 0; i < 4; i++) {
        e[i] = __expf(al[i] - mx);
        ssum += e[i];
    }
#pragma unroll
    for (int o = 16; o; o >>= 1) ssum += __shfl_xor_sync(0xffffffffu, ssum, o);
    __syncthreads();
    if (lane == 0) red[warp] = ssum;
    __syncthreads();
    float tot = 0.f;
#pragma unroll
    for (int i = 0; i < 8; i++) tot += red[i];
    float inv = 1.0f / tot;

    float* oa = out_att + (size_t)b * SS * TT + t;
#pragma unroll
    for (int i = 0; i < 4; i++) {
        int s = tid + i * 256;
        float w = e[i] * inv;
        ga[s] = w;
        oa[(size_t)s * TT] = w;
    }
}

// ---------------------------------------------------------------------------
// K4: context = attn @ states, split-S with atomicAdd epilogue.
// ---------------------------------------------------------------------------
__global__ __launch_bounds__(128) void ctx_kernel(const float* __restrict__ states,
                                                  float* __restrict__ out_ctx) {
    int dc = blockIdx.x, sc = blockIdx.y, b = blockIdx.z;
    int d = dc * 128 + threadIdx.x;
    int s0 = sc * 128;
    __shared__ float aw[TT][128];
    for (int i = threadIdx.x; i < TT * 128; i += 128) {
        int t = i >> 7, sl = i & 127;
        aw[t][sl] = g_attn[(size_t)(b * TT + t) * SS + s0 + sl];
    }
    __syncthreads();
    float acc[TT] = {};
    const float* sb = states + ((size_t)b * SS + s0) * H2 + d;
#pragma unroll 2
    for (int sl = 0; sl < 128; sl++) {
        float sv = sb[(size_t)sl * H2];
#pragma unroll
        for (int t = 0; t < TT; t++) acc[t] = fmaf(aw[t][sl], sv, acc[t]);
    }
#pragma unroll
    for (int t = 0; t < TT; t++)
        atomicAdd(&out_ctx[(size_t)(b * TT + t) * H2 + d], acc[t]);
}

// ---------------------------------------------------------------------------
// K5: attention_hidden = [context, query] @ Wc + bc, split-K with atomics.
// ---------------------------------------------------------------------------
__global__ __launch_bounds__(128) void hidden_kernel(const float* __restrict__ query,
                                                     const float* __restrict__ Wc,
                                                     const float* __restrict__ bc,
                                                     const float* __restrict__ ctx,
                                                     float* __restrict__ out_hid) {
    int hc = blockIdx.x, tg = blockIdx.y;
    int b = blockIdx.z >> 2, kc = blockIdx.z & 3;
    int h = hc * 128 + threadIdx.x;
    int t0 = tg * 8, k0 = kc * 384;
    __shared__ float cc[8][384];
    for (int i = threadIdx.x; i < 8 * 384; i += 128) {
        int r = i / 384, col = i - r * 384;
        int gk = k0 + col;
        cc[r][col] = (gk < H2)
                         ? ctx[(size_t)(b * TT + t0 + r) * H2 + gk]
                         : query[(size_t)(b * TT + t0 + r) * HH + gk - H2];
    }
    __syncthreads();
    float acc[8];
    float bias = (kc == 0) ? bc[h] : 0.f;
#pragma unroll
    for (int i = 0; i < 8; i++) acc[i] = bias;
#pragma unroll 4
    for (int k = 0; k < 384; k++) {
        float w = Wc[(size_t)(k0 + k) * HH + h];
#pragma unroll
        for (int i = 0; i < 8; i++) acc[i] = fmaf(cc[i][k], w, acc[i]);
    }
#pragma unroll
    for (int i = 0; i < 8; i++)
        atomicAdd(&out_hid[(size_t)(b * TT + t0 + i) * HH + h], acc[i]);
}

// ---------------------------------------------------------------------------
extern "C" void kernel_launch(void* const* d_in, const int* in_sizes, int n_in,
                              void* d_out, int out_size) {
    const float* query  = (const float*)d_in[0];
    const float* states = (const float*)d_in[1];
    const int*   mask   = (const int*)d_in[2];
    const float* Wq     = (const float*)d_in[3];
    const float* bq     = (const float*)d_in[4];
    const float* Ws     = (const float*)d_in[5];
    const float* v      = (const float*)d_in[6];
    const float* Wc     = (const float*)d_in[7];
    const float* bc     = (const float*)d_in[8];

    float* out_ctx = (float*)d_out;                  // (B,T,2H)
    float* out_hid = out_ctx + BB * TT * H2;         // (B,T,H)
    float* out_att = out_hid + BB * TT * HH;         // (B,S,T)

    zero_kernel<<<48, 256>>>((float4*)d_out);
    qf_kernel<<<dim3(8, 4, 4), 128>>>(query, Wq, bq);
    sf_sgemm<<<dim3(H2 / 128, (BB * SS) / 128), 256>>>(states, Ws);
    align_kernel<<<dim3(8, TT, BB), 256>>>(v, mask);
    softmax_kernel<<<dim3(TT, BB), 256>>>(out_att);
    ctx_kernel<<<dim3(8, 8, 4), 128>>>(states, out_ctx);
    hidden_kernel<<<dim3(4, 4, 16), 128>>>(query, Wc, bc, out_ctx, out_hid);
}

// round 4
// speedup vs baseline: 1.6158x; 1.2481x over previous
#include <cuda_runtime.h>
#include <cstdint>

#define BB 4
#define TT 32
#define SS 1024
#define HH 512
#define H2 1024
#define H3 1536

typedef unsigned long long ull;

// Scratch (allocation-free: __device__ globals)
__device__ float g_qf[BB * TT * H2];          // 512 KB
__device__ float g_sf[(size_t)BB * SS * H2];  // 16 MB
__device__ float g_attn[BB * TT * SS];        // 512 KB (raw alignments -> softmaxed in place)

__device__ __forceinline__ float tanh_fast(float x) {
    float y;
    asm("tanh.approx.f32 %0, %1;" : "=f"(y) : "f"(x));
    return y;
}

__device__ __forceinline__ ull pack_dup(float v) {
    ull r;
    asm("mov.b64 %0, {%1, %1};" : "=l"(r) : "f"(v));
    return r;
}

__device__ __forceinline__ void fma2(ull& c, ull a, ull b) {
    asm("fma.rn.f32x2 %0, %1, %2, %3;" : "=l"(c) : "l"(a), "l"(b), "l"(c));
}

// ---------------------------------------------------------------------------
// K0: zero out_ctx + out_hid (atomicAdd targets).
// ---------------------------------------------------------------------------
__global__ __launch_bounds__(256) void zero_kernel(float4* __restrict__ p) {
    int i = blockIdx.x * 1024 + threadIdx.x;
#pragma unroll
    for (int u = 0; u < 4; u++) p[i + u * 256] = make_float4(0.f, 0.f, 0.f, 0.f);
}

// ---------------------------------------------------------------------------
// K1: qf = query @ Wq + bq   (128 x 1024, K=512)
// ---------------------------------------------------------------------------
__global__ __launch_bounds__(128) void qf_kernel(const float* __restrict__ query,
                                                 const float* __restrict__ Wq,
                                                 const float* __restrict__ bq) {
    int jc = blockIdx.x, tg = blockIdx.y, b = blockIdx.z;
    int j = jc * 128 + threadIdx.x;
    int t0 = tg * 8;
    __shared__ float q_s[8][HH];
    for (int i = threadIdx.x; i < 8 * HH; i += 128) {
        int r = i >> 9, c = i & (HH - 1);
        q_s[r][c] = query[(size_t)(b * TT + t0 + r) * HH + c];
    }
    __syncthreads();
    float acc[8];
    float bias = bq[j];
#pragma unroll
    for (int i = 0; i < 8; i++) acc[i] = bias;
#pragma unroll 8
    for (int k = 0; k < HH; k++) {
        float w = Wq[(size_t)k * H2 + j];
#pragma unroll
        for (int i = 0; i < 8; i++) acc[i] = fmaf(q_s[i][k], w, acc[i]);
    }
#pragma unroll
    for (int i = 0; i < 8; i++)
        g_qf[(size_t)(b * TT + t0 + i) * H2 + j] = acc[i];
}

// ---------------------------------------------------------------------------
// K2: sf = states @ Ws  (M=4096, N=1024, K=1024). 128x128 tile, 256 threads,
// FFMA2 inner loop, register double-buffered global loads.
// ---------------------------------------------------------------------------
#define KSTEP 16
__global__ __launch_bounds__(256) void sf_sgemm(const float* __restrict__ A,
                                                const float* __restrict__ Bm) {
    const int N = H2, K = H2;
    __shared__ ull Asd[KSTEP][128];   // 16 KB
    __shared__ float Bs[KSTEP][128];  // 8 KB
    int tid = threadIdx.x;
    int tx = tid & 15, ty = tid >> 4;
    const float* Ab = A + (size_t)blockIdx.y * 128 * K;
    const float* Bb = Bm + blockIdx.x * 128;

    ull c[8][4];
#pragma unroll
    for (int i = 0; i < 8; i++)
#pragma unroll
        for (int j = 0; j < 4; j++) c[i][j] = 0ull;

    int arow = tid >> 1, acol = (tid & 1) * 8;
    int brow = tid >> 4, bcol = (tid & 15) * 8;

    const float* Aptr = Ab + (size_t)arow * K + acol;
    const float* Bptr = Bb + (size_t)brow * N + bcol;

    float4 av0 = *(const float4*)(Aptr);
    float4 av1 = *(const float4*)(Aptr + 4);
    float4 bv0 = *(const float4*)(Bptr);
    float4 bv1 = *(const float4*)(Bptr + 4);

    for (int k0 = 0; k0 < K; k0 += KSTEP) {
        Asd[acol + 0][arow] = pack_dup(av0.x);
        Asd[acol + 1][arow] = pack_dup(av0.y);
        Asd[acol + 2][arow] = pack_dup(av0.z);
        Asd[acol + 3][arow] = pack_dup(av0.w);
        Asd[acol + 4][arow] = pack_dup(av1.x);
        Asd[acol + 5][arow] = pack_dup(av1.y);
        Asd[acol + 6][arow] = pack_dup(av1.z);
        Asd[acol + 7][arow] = pack_dup(av1.w);
        *(float4*)&Bs[brow][bcol] = bv0;
        *(float4*)&Bs[brow][bcol + 4] = bv1;
        __syncthreads();
        if (k0 + KSTEP < K) {
            av0 = *(const float4*)(Aptr + k0 + KSTEP);
            av1 = *(const float4*)(Aptr + k0 + KSTEP + 4);
            bv0 = *(const float4*)(Bptr + (size_t)(k0 + KSTEP) * N);
            bv1 = *(const float4*)(Bptr + (size_t)(k0 + KSTEP) * N + 4);
        }
#pragma unroll
        for (int k = 0; k < KSTEP; k++) {
            ull a[8];
#pragma unroll
            for (int i = 0; i < 8; i++) a[i] = Asd[k][ty * 8 + i];
            ull b[4];
            float4 bq0 = *(float4*)&Bs[k][tx * 8];
            float4 bq1 = *(float4*)&Bs[k][tx * 8 + 4];
            b[0] = *(ull*)&bq0.x; b[1] = *(ull*)&bq0.z;
            b[2] = *(ull*)&bq1.x; b[3] = *(ull*)&bq1.z;
#pragma unroll
            for (int i = 0; i < 8; i++)
#pragma unroll
                for (int j = 0; j < 4; j++) fma2(c[i][j], a[i], b[j]);
        }
        __syncthreads();
    }
    float* Cb = g_sf + (size_t)(blockIdx.y * 128 + ty * 8) * N + blockIdx.x * 128 + tx * 8;
#pragma unroll
    for (int i = 0; i < 8; i++) {
#pragma unroll
        for (int j = 0; j < 4; j++)
            *(ull*)(Cb + (size_t)i * N + 2 * j) = c[i][j];
    }
}

// ---------------------------------------------------------------------------
// K3a: raw alignments with qf reuse from smem.
// Block = (sc, b): s-chunk of 32 rows, ALL 32 t. 512 threads (16 warps), one
// block per SM (128 blocks = 1 wave). qf[b] (32t x 1024d = 128KB) in dynamic
// smem; warp loads its sf row into regs ONCE and reuses over all 32 t.
// Global sf traffic: 16MB total (read once) vs 512MB before.
// Lane owns interleaved d = u*128 + lane*4 -> conflict-free LDS.128 on qf and
// coalesced LDG.128 on sf/v.
// ---------------------------------------------------------------------------
__global__ __launch_bounds__(512, 1) void align_kernel(const float* __restrict__ v) {
    extern __shared__ float qf_s[];  // [TT][H2] = 128 KB
    int sc = blockIdx.x, b = blockIdx.y;
    int tid = threadIdx.x, lane = tid & 31, warp = tid >> 5;

    // cooperative load of qf[b] into smem (32768 floats = 8192 float4)
    const float4* qsrc = (const float4*)(g_qf + (size_t)b * TT * H2);
    float4* qdst = (float4*)qf_s;
#pragma unroll
    for (int i = 0; i < 16; i++) qdst[tid + i * 512] = qsrc[tid + i * 512];

    float4 vr[8];
#pragma unroll
    for (int u = 0; u < 8; u++) vr[u] = *(const float4*)(v + u * 128 + lane * 4);
    __syncthreads();

#pragma unroll 1
    for (int si = 0; si < 2; si++) {
        int s = sc * 32 + warp * 2 + si;
        const float* sfrow = g_sf + ((size_t)(b * SS + s)) * H2;
        float4 sv[8];
#pragma unroll
        for (int u = 0; u < 8; u++)
            sv[u] = *(const float4*)(sfrow + u * 128 + lane * 4);

        float* ga = g_attn + (size_t)(b * TT) * SS + s;
#pragma unroll 1
        for (int t = 0; t < TT; t++) {
            const float* qrow = qf_s + t * H2;
            float a0 = 0.f, a1 = 0.f, a2 = 0.f, a3 = 0.f;
#pragma unroll
            for (int u = 0; u < 8; u++) {
                float4 q = *(const float4*)(qrow + u * 128 + lane * 4);
                a0 = fmaf(tanh_fast(q.x + sv[u].x), vr[u].x, a0);
                a1 = fmaf(tanh_fast(q.y + sv[u].y), vr[u].y, a1);
                a2 = fmaf(tanh_fast(q.z + sv[u].z), vr[u].z, a2);
                a3 = fmaf(tanh_fast(q.w + sv[u].w), vr[u].w, a3);
            }
            float acc = (a0 + a1) + (a2 + a3);
#pragma unroll
            for (int o = 16; o; o >>= 1) acc += __shfl_xor_sync(0xffffffffu, acc, o);
            if (lane == 0) ga[(size_t)t * SS] = acc;
        }
    }
}

// ---------------------------------------------------------------------------
// K3b: mask + softmax over S=1024 per (b,t); writes g_attn in place + out_att.
// ---------------------------------------------------------------------------
__global__ __launch_bounds__(256) void softmax_kernel(const int* __restrict__ mask,
                                                      float* __restrict__ out_att) {
    int t = blockIdx.x, b = blockIdx.y;
    int tid = threadIdx.x, lane = tid & 31, warp = tid >> 5;
    __shared__ float red[8];

    float* ga = g_attn + (size_t)(b * TT + t) * SS;
    float al[4];
#pragma unroll
    for (int i = 0; i < 4; i++) {
        int s = tid + i * 256;
        al[i] = mask[b * SS + s] ? ga[s] : -1e30f;
    }

    float m = fmaxf(fmaxf(al[0], al[1]), fmaxf(al[2], al[3]));
#pragma unroll
    for (int o = 16; o; o >>= 1) m = fmaxf(m, __shfl_xor_sync(0xffffffffu, m, o));
    if (lane == 0) red[warp] = m;
    __syncthreads();
    float mx = -1e30f;
#pragma unroll
    for (int i = 0; i < 8; i++) mx = fmaxf(mx, red[i]);

    float e[4];
    float ssum = 0.f;
#pragma unroll
    for (int i = 0; i < 4; i++) {
        e[i] = __expf(al[i] - mx);
        ssum += e[i];
    }
#pragma unroll
    for (int o = 16; o; o >>= 1) ssum += __shfl_xor_sync(0xffffffffu, ssum, o);
    __syncthreads();
    if (lane == 0) red[warp] = ssum;
    __syncthreads();
    float tot = 0.f;
#pragma unroll
    for (int i = 0; i < 8; i++) tot += red[i];
    float inv = 1.0f / tot;

    float* oa = out_att + (size_t)b * SS * TT + t;
#pragma unroll
    for (int i = 0; i < 4; i++) {
        int s = tid + i * 256;
        float w = e[i] * inv;
        ga[s] = w;
        oa[(size_t)s * TT] = w;
    }
}

// ---------------------------------------------------------------------------
// K4: context = attn @ states, split-S with atomicAdd epilogue.
// ---------------------------------------------------------------------------
__global__ __launch_bounds__(128) void ctx_kernel(const float* __restrict__ states,
                                                  float* __restrict__ out_ctx) {
    int dc = blockIdx.x, sc = blockIdx.y, b = blockIdx.z;
    int d = dc * 128 + threadIdx.x;
    int s0 = sc * 128;
    __shared__ float aw[TT][128];
    for (int i = threadIdx.x; i < TT * 128; i += 128) {
        int t = i >> 7, sl = i & 127;
        aw[t][sl] = g_attn[(size_t)(b * TT + t) * SS + s0 + sl];
    }
    __syncthreads();
    float acc[TT] = {};
    const float* sb = states + ((size_t)b * SS + s0) * H2 + d;
#pragma unroll 2
    for (int sl = 0; sl < 128; sl++) {
        float sv = sb[(size_t)sl * H2];
#pragma unroll
        for (int t = 0; t < TT; t++) acc[t] = fmaf(aw[t][sl], sv, acc[t]);
    }
#pragma unroll
    for (int t = 0; t < TT; t++)
        atomicAdd(&out_ctx[(size_t)(b * TT + t) * H2 + d], acc[t]);
}

// ---------------------------------------------------------------------------
// K5: attention_hidden = [context, query] @ Wc + bc, split-K with atomics.
// ---------------------------------------------------------------------------
__global__ __launch_bounds__(128) void hidden_kernel(const float* __restrict__ query,
                                                     const float* __restrict__ Wc,
                                                     const float* __restrict__ bc,
                                                     const float* __restrict__ ctx,
                                                     float* __restrict__ out_hid) {
    int hc = blockIdx.x, tg = blockIdx.y;
    int b = blockIdx.z >> 2, kc = blockIdx.z & 3;
    int h = hc * 128 + threadIdx.x;
    int t0 = tg * 8, k0 = kc * 384;
    __shared__ float cc[8][384];
    for (int i = threadIdx.x; i < 8 * 384; i += 128) {
        int r = i / 384, col = i - r * 384;
        int gk = k0 + col;
        cc[r][col] = (gk < H2)
                         ? ctx[(size_t)(b * TT + t0 + r) * H2 + gk]
                         : query[(size_t)(b * TT + t0 + r) * HH + gk - H2];
    }
    __syncthreads();
    float acc[8];
    float bias = (kc == 0) ? bc[h] : 0.f;
#pragma unroll
    for (int i = 0; i < 8; i++) acc[i] = bias;
#pragma unroll 4
    for (int k = 0; k < 384; k++) {
        float w = Wc[(size_t)(k0 + k) * HH + h];
#pragma unroll
        for (int i = 0; i < 8; i++) acc[i] = fmaf(cc[i][k], w, acc[i]);
    }
#pragma unroll
    for (int i = 0; i < 8; i++)
        atomicAdd(&out_hid[(size_t)(b * TT + t0 + i) * HH + h], acc[i]);
}

// ---------------------------------------------------------------------------
extern "C" void kernel_launch(void* const* d_in, const int* in_sizes, int n_in,
                              void* d_out, int out_size) {
    const float* query  = (const float*)d_in[0];
    const float* states = (const float*)d_in[1];
    const int*   mask   = (const int*)d_in[2];
    const float* Wq     = (const float*)d_in[3];
    const float* bq     = (const float*)d_in[4];
    const float* Ws     = (const float*)d_in[5];
    const float* v      = (const float*)d_in[6];
    const float* Wc     = (const float*)d_in[7];
    const float* bc     = (const float*)d_in[8];

    float* out_ctx = (float*)d_out;                  // (B,T,2H)
    float* out_hid = out_ctx + BB * TT * H2;         // (B,T,H)
    float* out_att = out_hid + BB * TT * HH;         // (B,S,T)

    static int smem_set = 0;
    if (!smem_set) {
        cudaFuncSetAttribute(align_kernel,
                             cudaFuncAttributeMaxDynamicSharedMemorySize,
                             TT * H2 * sizeof(float));
        smem_set = 1;
    }

    zero_kernel<<<48, 256>>>((float4*)d_out);
    qf_kernel<<<dim3(8, 4, 4), 128>>>(query, Wq, bq);
    sf_sgemm<<<dim3(H2 / 128, (BB * SS) / 128), 256>>>(states, Ws);
    align_kernel<<<dim3(32, BB), 512, TT * H2 * sizeof(float)>>>(v);
    softmax_kernel<<<dim3(TT, BB), 256>>>(mask, out_att);
    ctx_kernel<<<dim3(8, 8, 4), 128>>>(states, out_ctx);
    hidden_kernel<<<dim3(4, 4, 16), 128>>>(query, Wc, bc, out_ctx, out_hid);
}

// round 6
// speedup vs baseline: 2.3320x; 1.4433x over previous
#include <cuda_runtime.h>
#include <cuda_bf16.h>
#include <cstdint>

#define BB 4
#define TT 32
#define SS 1024
#define HH 512
#define H2 1024
#define H3 1536

typedef unsigned long long ull;

// ---------------------------------------------------------------------------
// Scratch (allocation-free: __device__ globals)
// ---------------------------------------------------------------------------
__device__ float g_qf[BB * TT * H2];          // 512 KB
__device__ float g_sf[(size_t)BB * SS * H2];  // 16 MB
__device__ float g_attn[BB * TT * SS];        // 512 KB
// bf16 hi/lo split operands, plain row-major K-major layouts:
// gA_*: [4096][1024] bf16 (states),  gB_*: [1024 n][1024 k] bf16 (Ws^T)
__device__ __align__(16) char gA_hi[8 << 20];
__device__ __align__(16) char gA_lo[8 << 20];
__device__ __align__(16) char gB_hi[2 << 20];
__device__ __align__(16) char gB_lo[2 << 20];

__device__ __forceinline__ float tanh_fast(float x) {
    float y;
    asm("tanh.approx.f32 %0, %1;" : "=f"(y) : "f"(x));
    return y;
}

__device__ __forceinline__ uint32_t smem_u32(const void* p) {
    uint32_t a;
    asm("{ .reg .u64 t; cvta.to.shared.u64 t, %1; cvt.u32.u64 %0, t; }" : "=r"(a) : "l"(p));
    return a;
}

__device__ __forceinline__ uint32_t pack2bf(float a, float b) {
    __nv_bfloat162 h = __floats2bfloat162_rn(a, b);
    return *(uint32_t*)&h;
}

// ---- baseline-PTX tensor ops (sm_80+: compile fine for plain sm_103) ------
#define LDSM_X4(r, a) \
    asm volatile("ldmatrix.sync.aligned.m8n8.x4.shared.b16 {%0,%1,%2,%3}, [%4];" \
                 : "=r"((r)[0]), "=r"((r)[1]), "=r"((r)[2]), "=r"((r)[3]) : "r"(a))

__device__ __forceinline__ void hmma(float* c, const uint32_t* a, uint32_t b0, uint32_t b1) {
    asm volatile(
        "mma.sync.aligned.m16n8k16.row.col.f32.bf16.bf16.f32 "
        "{%0,%1,%2,%3}, {%4,%5,%6,%7}, {%8,%9}, {%0,%1,%2,%3};"
        : "+f"(c[0]), "+f"(c[1]), "+f"(c[2]), "+f"(c[3])
        : "r"(a[0]), "r"(a[1]), "r"(a[2]), "r"(a[3]), "r"(b0), "r"(b1));
}

#define CP16(s, g) \
    asm volatile("cp.async.cg.shared.global [%0], [%1], 16;" :: "r"(s), "l"(g))
#define CPCOMMIT() asm volatile("cp.async.commit_group;" ::: "memory")
#define CPWAIT1() asm volatile("cp.async.wait_group 1;" ::: "memory")
#define CPWAIT0() asm volatile("cp.async.wait_group 0;" ::: "memory")

// ---------------------------------------------------------------------------
// K0: zero out_ctx + out_hid (atomicAdd targets).
// ---------------------------------------------------------------------------
__global__ __launch_bounds__(256) void zero_kernel(float4* __restrict__ p) {
    int i = blockIdx.x * 1024 + threadIdx.x;
#pragma unroll
    for (int u = 0; u < 4; u++) p[i + u * 256] = make_float4(0.f, 0.f, 0.f, 0.f);
}

// ---------------------------------------------------------------------------
// K1: qf = query @ Wq + bq   (128 x 1024, K=512)
// ---------------------------------------------------------------------------
__global__ __launch_bounds__(128) void qf_kernel(const float* __restrict__ query,
                                                 const float* __restrict__ Wq,
                                                 const float* __restrict__ bq) {
    int jc = blockIdx.x, tg = blockIdx.y, b = blockIdx.z;
    int j = jc * 128 + threadIdx.x;
    int t0 = tg * 8;
    __shared__ float q_s[8][HH];
    for (int i = threadIdx.x; i < 8 * HH; i += 128) {
        int r = i >> 9, c = i & (HH - 1);
        q_s[r][c] = query[(size_t)(b * TT + t0 + r) * HH + c];
    }
    __syncthreads();
    float acc[8];
    float bias = bq[j];
#pragma unroll
    for (int i = 0; i < 8; i++) acc[i] = bias;
#pragma unroll 8
    for (int k = 0; k < HH; k++) {
        float w = Wq[(size_t)k * H2 + j];
#pragma unroll
        for (int i = 0; i < 8; i++) acc[i] = fmaf(q_s[i][k], w, acc[i]);
    }
#pragma unroll
    for (int i = 0; i < 8; i++)
        g_qf[(size_t)(b * TT + t0 + i) * H2 + j] = acc[i];
}

// ---------------------------------------------------------------------------
// prep_A: states fp32 [4096,1024] -> gA_hi/gA_lo bf16 row-major.
// ---------------------------------------------------------------------------
__global__ __launch_bounds__(256) void prep_A(const float* __restrict__ A) {
    int idx = blockIdx.x * 256 + threadIdx.x;
#pragma unroll
    for (int q = 0; q < 4; q++) {
        int fid = idx * 4 + q;  // float4 index over [4096][1024]
        float4 vvv = *(const float4*)(A + (size_t)fid * 4);
        float h0 = __bfloat162float(__float2bfloat16_rn(vvv.x));
        float h1 = __bfloat162float(__float2bfloat16_rn(vvv.y));
        float h2 = __bfloat162float(__float2bfloat16_rn(vvv.z));
        float h3 = __bfloat162float(__float2bfloat16_rn(vvv.w));
        ull hi = (ull)pack2bf(h0, h1) | ((ull)pack2bf(h2, h3) << 32);
        ull lo = (ull)pack2bf(vvv.x - h0, vvv.y - h1) |
                 ((ull)pack2bf(vvv.z - h2, vvv.w - h3) << 32);
        *(ull*)(gA_hi + (size_t)fid * 8) = hi;
        *(ull*)(gA_lo + (size_t)fid * 8) = lo;
    }
}

// ---------------------------------------------------------------------------
// prep_B: Ws fp32 [K=1024, N=1024] -> gB_hi/gB_lo bf16 transposed [N][K].
// Block transposes 64x64 via smem. grid (kt=16, nb=16), 256 thr.
// ---------------------------------------------------------------------------
__global__ __launch_bounds__(256) void prep_B(const float* __restrict__ W) {
    __shared__ float tr[64][65];
    int k0 = blockIdx.x * 64, n0 = blockIdx.y * 64;
    int tid = threadIdx.x;
    int ki = tid >> 2, nq = (tid & 3) * 16;
#pragma unroll
    for (int j = 0; j < 4; j++) {
        float4 vv = *(const float4*)(W + (size_t)(k0 + ki) * H2 + n0 + nq + j * 4);
        tr[nq + j * 4 + 0][ki] = vv.x;
        tr[nq + j * 4 + 1][ki] = vv.y;
        tr[nq + j * 4 + 2][ki] = vv.z;
        tr[nq + j * 4 + 3][ki] = vv.w;
    }
    __syncthreads();
    int nr_l = tid >> 2, kq = (tid & 3) * 16;
    int n_g = n0 + nr_l;
#pragma unroll
    for (int j = 0; j < 4; j++) {
        int kr = kq + j * 4;
        float x0 = tr[nr_l][kr], x1 = tr[nr_l][kr + 1];
        float x2 = tr[nr_l][kr + 2], x3 = tr[nr_l][kr + 3];
        float h0 = __bfloat162float(__float2bfloat16_rn(x0));
        float h1 = __bfloat162float(__float2bfloat16_rn(x1));
        float h2 = __bfloat162float(__float2bfloat16_rn(x2));
        float h3 = __bfloat162float(__float2bfloat16_rn(x3));
        ull hi = (ull)pack2bf(h0, h1) | ((ull)pack2bf(h2, h3) << 32);
        ull lo = (ull)pack2bf(x0 - h0, x1 - h1) |
                 ((ull)pack2bf(x2 - h2, x3 - h3) << 32);
        size_t off = ((size_t)n_g * H2 + k0 + kr) * 2;
        *(ull*)(gB_hi + off) = hi;
        *(ull*)(gB_lo + off) = lo;
    }
}

// ---------------------------------------------------------------------------
// K2: sf = states @ Ws via mma.sync bf16 3-MMA split (Ah*Bh + Ah*Bl + Al*Bh).
// Block 128x128, 8 warps of 64x32, K-chunks of 64, cp.async double buffer.
// smem rows padded to 144B -> conflict-free ldmatrix. grid (nt=8, mt=32).
// ---------------------------------------------------------------------------
#define ROWB 144
#define TILEB (128 * ROWB)   // 18432
#define STAGEB (4 * TILEB)   // 73728
#define SMEM_MMA (2 * STAGEB)

__device__ __forceinline__ void load_chunk(uint32_t sst, const char* gAh, const char* gAl,
                                           const char* gBh, const char* gBl,
                                           int c, int tid) {
#pragma unroll
    for (int r = 0; r < 4; r++) {
        int i = r * 256 + tid;
        int row = i >> 3, quad = i & 7;
        uint32_t soff = row * ROWB + quad * 16;
        size_t goff = (size_t)row * 2048 + (size_t)c * 128 + quad * 16;
        CP16(sst + soff, gAh + goff);
        CP16(sst + TILEB + soff, gAl + goff);
        CP16(sst + 2 * TILEB + soff, gBh + goff);
        CP16(sst + 3 * TILEB + soff, gBl + goff);
    }
}

__global__ __launch_bounds__(256, 1) void sf_mma() {
    extern __shared__ __align__(16) char sm[];
    uint32_t sbase = smem_u32(sm);
    int tid = threadIdx.x, lane = tid & 31, warp = tid >> 5;
    int nt = blockIdx.x, mt = blockIdx.y;
    int wm = warp >> 2, wn = warp & 3;  // warp tile: m = wm*64, n = wn*32

    const char* gAh = gA_hi + (size_t)(mt * 128) * 2048;
    const char* gAl = gA_lo + (size_t)(mt * 128) * 2048;
    const char* gBh = gB_hi + (size_t)(nt * 128) * 2048;
    const char* gBl = gB_lo + (size_t)(nt * 128) * 2048;

    float cacc[4][4][4] = {};

    load_chunk(sbase, gAh, gAl, gBh, gBl, 0, tid);
    CPCOMMIT();

#pragma unroll 1
    for (int c = 0; c < 16; c++) {
        int cur = c & 1;
        if (c + 1 < 16) {
            load_chunk(sbase + (cur ^ 1) * STAGEB, gAh, gAl, gBh, gBl, c + 1, tid);
            CPCOMMIT();
            CPWAIT1();
        } else {
            CPWAIT0();
        }
        __syncthreads();

        uint32_t sA_h = sbase + cur * STAGEB;
        uint32_t sA_l = sA_h + TILEB;
        uint32_t sB_h = sA_h + 2 * TILEB;
        uint32_t sB_l = sA_h + 3 * TILEB;
        int r16 = lane & 15, hx = lane >> 4;

#pragma unroll
        for (int k16 = 0; k16 < 4; k16++) {
            int kb = k16 * 32 + hx * 16;
            uint32_t ah[4][4], bh[2][4];
#pragma unroll
            for (int mf = 0; mf < 4; mf++)
                LDSM_X4(ah[mf], sA_h + (wm * 64 + mf * 16 + r16) * ROWB + kb);
#pragma unroll
            for (int h = 0; h < 2; h++)
                LDSM_X4(bh[h], sB_h + (wn * 32 + h * 16 + r16) * ROWB + kb);
#pragma unroll
            for (int mf = 0; mf < 4; mf++)
#pragma unroll
                for (int nf = 0; nf < 4; nf++)
                    hmma(cacc[mf][nf], ah[mf], bh[nf >> 1][nf & 1], bh[nf >> 1][(nf & 1) + 2]);

            uint32_t bl[2][4];
#pragma unroll
            for (int h = 0; h < 2; h++)
                LDSM_X4(bl[h], sB_l + (wn * 32 + h * 16 + r16) * ROWB + kb);
#pragma unroll
            for (int mf = 0; mf < 4; mf++)
#pragma unroll
                for (int nf = 0; nf < 4; nf++)
                    hmma(cacc[mf][nf], ah[mf], bl[nf >> 1][nf & 1], bl[nf >> 1][(nf & 1) + 2]);

            uint32_t al[4][4];
#pragma unroll
            for (int mf = 0; mf < 4; mf++)
                LDSM_X4(al[mf], sA_l + (wm * 64 + mf * 16 + r16) * ROWB + kb);
#pragma unroll
            for (int mf = 0; mf < 4; mf++)
#pragma unroll
                for (int nf = 0; nf < 4; nf++)
                    hmma(cacc[mf][nf], al[mf], bh[nf >> 1][nf & 1], bh[nf >> 1][(nf & 1) + 2]);
        }
        __syncthreads();
    }

    // epilogue: c0,c1 -> (row, col..col+1); c2,c3 -> (row+8, ...)
    int tg = lane >> 2, tq = lane & 3;
#pragma unroll
    for (int mf = 0; mf < 4; mf++) {
#pragma unroll
        for (int nf = 0; nf < 4; nf++) {
            float* base = g_sf + (size_t)(mt * 128 + wm * 64 + mf * 16 + tg) * H2 +
                          nt * 128 + wn * 32 + nf * 8 + tq * 2;
            float2 v0 = {cacc[mf][nf][0], cacc[mf][nf][1]};
            float2 v1 = {cacc[mf][nf][2], cacc[mf][nf][3]};
            *(float2*)base = v0;
            *(float2*)(base + 8 * H2) = v1;
        }
    }
}

// ---------------------------------------------------------------------------
// K3a: raw alignments with qf reuse from smem (MUFU-floor bound).
// ---------------------------------------------------------------------------
__global__ __launch_bounds__(512, 1) void align_kernel(const float* __restrict__ v) {
    extern __shared__ float qf_s[];  // [TT][H2] = 128 KB
    int sc = blockIdx.x, b = blockIdx.y;
    int tid = threadIdx.x, lane = tid & 31, warp = tid >> 5;

    const float4* qsrc = (const float4*)(g_qf + (size_t)b * TT * H2);
    float4* qdst = (float4*)qf_s;
#pragma unroll
    for (int i = 0; i < 16; i++) qdst[tid + i * 512] = qsrc[tid + i * 512];

    float4 vr[8];
#pragma unroll
    for (int u = 0; u < 8; u++) vr[u] = *(const float4*)(v + u * 128 + lane * 4);
    __syncthreads();

#pragma unroll 1
    for (int si = 0; si < 2; si++) {
        int s = sc * 32 + warp * 2 + si;
        const float* sfrow = g_sf + ((size_t)(b * SS + s)) * H2;
        float4 sv[8];
#pragma unroll
        for (int u = 0; u < 8; u++)
            sv[u] = *(const float4*)(sfrow + u * 128 + lane * 4);

        float* ga = g_attn + (size_t)(b * TT) * SS + s;
#pragma unroll 1
        for (int t = 0; t < TT; t++) {
            const float* qrow = qf_s + t * H2;
            float a0 = 0.f, a1 = 0.f, a2 = 0.f, a3 = 0.f;
#pragma unroll
            for (int u = 0; u < 8; u++) {
                float4 q = *(const float4*)(qrow + u * 128 + lane * 4);
                a0 = fmaf(tanh_fast(q.x + sv[u].x), vr[u].x, a0);
                a1 = fmaf(tanh_fast(q.y + sv[u].y), vr[u].y, a1);
                a2 = fmaf(tanh_fast(q.z + sv[u].z), vr[u].z, a2);
                a3 = fmaf(tanh_fast(q.w + sv[u].w), vr[u].w, a3);
            }
            float acc = (a0 + a1) + (a2 + a3);
#pragma unroll
            for (int o = 16; o; o >>= 1) acc += __shfl_xor_sync(0xffffffffu, acc, o);
            if (lane == 0) ga[(size_t)t * SS] = acc;
        }
    }
}

// ---------------------------------------------------------------------------
// K3b: mask + softmax.
// ---------------------------------------------------------------------------
__global__ __launch_bounds__(256) void softmax_kernel(const int* __restrict__ mask,
                                                      float* __restrict__ out_att) {
    int t = blockIdx.x, b = blockIdx.y;
    int tid = threadIdx.x, lane = tid & 31, warp = tid >> 5;
    __shared__ float red[8];

    float* ga = g_attn + (size_t)(b * TT + t) * SS;
    float al[4];
#pragma unroll
    for (int i = 0; i < 4; i++) {
        int s = tid + i * 256;
        al[i] = mask[b * SS + s] ? ga[s] : -1e30f;
    }

    float m = fmaxf(fmaxf(al[0], al[1]), fmaxf(al[2], al[3]));
#pragma unroll
    for (int o = 16; o; o >>= 1) m = fmaxf(m, __shfl_xor_sync(0xffffffffu, m, o));
    if (lane == 0) red[warp] = m;
    __syncthreads();
    float mx = -1e30f;
#pragma unroll
    for (int i = 0; i < 8; i++) mx = fmaxf(mx, red[i]);

    float e[4];
    float ssum = 0.f;
#pragma unroll
    for (int i = 0; i < 4; i++) {
        e[i] = __expf(al[i] - mx);
        ssum += e[i];
    }
#pragma unroll
    for (int o = 16; o; o >>= 1) ssum += __shfl_xor_sync(0xffffffffu, ssum, o);
    __syncthreads();
    if (lane == 0) red[warp] = ssum;
    __syncthreads();
    float tot = 0.f;
#pragma unroll
    for (int i = 0; i < 8; i++) tot += red[i];
    float inv = 1.0f / tot;

    float* oa = out_att + (size_t)b * SS * TT + t;
#pragma unroll
    for (int i = 0; i < 4; i++) {
        int s = tid + i * 256;
        float w = e[i] * inv;
        ga[s] = w;
        oa[(size_t)s * TT] = w;
    }
}

// ---------------------------------------------------------------------------
// K4: context = attn @ states, split-S with atomicAdd epilogue.
// ---------------------------------------------------------------------------
__global__ __launch_bounds__(128) void ctx_kernel(const float* __restrict__ states,
                                                  float* __restrict__ out_ctx) {
    int dc = blockIdx.x, sc = blockIdx.y, b = blockIdx.z;
    int d = dc * 128 + threadIdx.x;
    int s0 = sc * 128;
    __shared__ float aw[TT][128];
    for (int i = threadIdx.x; i < TT * 128; i += 128) {
        int t = i >> 7, sl = i & 127;
        aw[t][sl] = g_attn[(size_t)(b * TT + t) * SS + s0 + sl];
    }
    __syncthreads();
    float acc[TT] = {};
    const float* sb = states + ((size_t)b * SS + s0) * H2 + d;
#pragma unroll 2
    for (int sl = 0; sl < 128; sl++) {
        float sv = sb[(size_t)sl * H2];
#pragma unroll
        for (int t = 0; t < TT; t++) acc[t] = fmaf(aw[t][sl], sv, acc[t]);
    }
#pragma unroll
    for (int t = 0; t < TT; t++)
        atomicAdd(&out_ctx[(size_t)(b * TT + t) * H2 + d], acc[t]);
}

// ---------------------------------------------------------------------------
// K5: attention_hidden = [context, query] @ Wc + bc, split-K with atomics.
// ---------------------------------------------------------------------------
__global__ __launch_bounds__(128) void hidden_kernel(const float* __restrict__ query,
                                                     const float* __restrict__ Wc,
                                                     const float* __restrict__ bc,
                                                     const float* __restrict__ ctx,
                                                     float* __restrict__ out_hid) {
    int hc = blockIdx.x, tg = blockIdx.y;
    int b = blockIdx.z >> 2, kc = blockIdx.z & 3;
    int h = hc * 128 + threadIdx.x;
    int t0 = tg * 8, k0 = kc * 384;
    __shared__ float cc[8][384];
    for (int i = threadIdx.x; i < 8 * 384; i += 128) {
        int r = i / 384, col = i - r * 384;
        int gk = k0 + col;
        cc[r][col] = (gk < H2)
                         ? ctx[(size_t)(b * TT + t0 + r) * H2 + gk]
                         : query[(size_t)(b * TT + t0 + r) * HH + gk - H2];
    }
    __syncthreads();
    float acc[8];
    float bias = (kc == 0) ? bc[h] : 0.f;
#pragma unroll
    for (int i = 0; i < 8; i++) acc[i] = bias;
#pragma unroll 4
    for (int k = 0; k < 384; k++) {
        float w = Wc[(size_t)(k0 + k) * HH + h];
#pragma unroll
        for (int i = 0; i < 8; i++) acc[i] = fmaf(cc[i][k], w, acc[i]);
    }
#pragma unroll
    for (int i = 0; i < 8; i++)
        atomicAdd(&out_hid[(size_t)(b * TT + t0 + i) * HH + h], acc[i]);
}

// ---------------------------------------------------------------------------
extern "C" void kernel_launch(void* const* d_in, const int* in_sizes, int n_in,
                              void* d_out, int out_size) {
    const float* query  = (const float*)d_in[0];
    const float* states = (const float*)d_in[1];
    const int*   mask   = (const int*)d_in[2];
    const float* Wq     = (const float*)d_in[3];
    const float* bq     = (const float*)d_in[4];
    const float* Ws     = (const float*)d_in[5];
    const float* v      = (const float*)d_in[6];
    const float* Wc     = (const float*)d_in[7];
    const float* bc     = (const float*)d_in[8];

    float* out_ctx = (float*)d_out;                  // (B,T,2H)
    float* out_hid = out_ctx + BB * TT * H2;         // (B,T,H)
    float* out_att = out_hid + BB * TT * HH;         // (B,S,T)

    static int attr_set = 0;
    if (!attr_set) {
        cudaFuncSetAttribute(align_kernel,
                             cudaFuncAttributeMaxDynamicSharedMemorySize,
                             TT * H2 * sizeof(float));
        cudaFuncSetAttribute(sf_mma,
                             cudaFuncAttributeMaxDynamicSharedMemorySize,
                             SMEM_MMA);
        attr_set = 1;
    }

    zero_kernel<<<48, 256>>>((float4*)d_out);
    qf_kernel<<<dim3(8, 4, 4), 128>>>(query, Wq, bq);
    prep_A<<<1024, 256>>>(states);
    prep_B<<<dim3(16, 16), 256>>>(Ws);
    sf_mma<<<dim3(8, 32), 256, SMEM_MMA>>>();
    align_kernel<<<dim3(32, BB), 512, TT * H2 * sizeof(float)>>>(v);
    softmax_kernel<<<dim3(TT, BB), 256>>>(mask, out_att);
    ctx_kernel<<<dim3(8, 8, 4), 128>>>(states, out_ctx);
    hidden_kernel<<<dim3(4, 4, 16), 128>>>(query, Wc, bc, out_ctx, out_hid);
}

// round 7
// speedup vs baseline: 2.7044x; 1.1597x over previous
#include <cuda_runtime.h>
#include <cuda_bf16.h>
#include <cstdint>

#define BB 4
#define TT 32
#define SS 1024
#define HH 512
#define H2 1024
#define H3 1536

typedef unsigned long long ull;

// ---------------------------------------------------------------------------
// Scratch (allocation-free: __device__ globals)
// ---------------------------------------------------------------------------
__device__ float g_qf[BB * TT * H2];          // 512 KB
__device__ float g_sf[(size_t)BB * SS * H2];  // 16 MB
__device__ float g_attn[BB * TT * SS];        // 512 KB
// bf16 hi/lo split operands, plain row-major K-major layouts:
// gA_*: [4096][1024] bf16 (states),  gB_*: [1024 n][1024 k] bf16 (Ws^T)
__device__ __align__(16) char gA_hi[8 << 20];
__device__ __align__(16) char gA_lo[8 << 20];
__device__ __align__(16) char gB_hi[2 << 20];
__device__ __align__(16) char gB_lo[2 << 20];

__device__ __forceinline__ float tanh_fast(float x) {
    float y;
    asm("tanh.approx.f32 %0, %1;" : "=f"(y) : "f"(x));
    return y;
}

__device__ __forceinline__ uint32_t smem_u32(const void* p) {
    uint32_t a;
    asm("{ .reg .u64 t; cvta.to.shared.u64 t, %1; cvt.u32.u64 %0, t; }" : "=r"(a) : "l"(p));
    return a;
}

__device__ __forceinline__ uint32_t pack2bf(float a, float b) {
    __nv_bfloat162 h = __floats2bfloat162_rn(a, b);
    return *(uint32_t*)&h;
}

// ---- baseline-PTX tensor ops (sm_80+: compile fine for plain sm_103) ------
#define LDSM_X4(r, a) \
    asm volatile("ldmatrix.sync.aligned.m8n8.x4.shared.b16 {%0,%1,%2,%3}, [%4];" \
                 : "=r"((r)[0]), "=r"((r)[1]), "=r"((r)[2]), "=r"((r)[3]) : "r"(a))

__device__ __forceinline__ void hmma(float* c, const uint32_t* a, uint32_t b0, uint32_t b1) {
    asm volatile(
        "mma.sync.aligned.m16n8k16.row.col.f32.bf16.bf16.f32 "
        "{%0,%1,%2,%3}, {%4,%5,%6,%7}, {%8,%9}, {%0,%1,%2,%3};"
        : "+f"(c[0]), "+f"(c[1]), "+f"(c[2]), "+f"(c[3])
        : "r"(a[0]), "r"(a[1]), "r"(a[2]), "r"(a[3]), "r"(b0), "r"(b1));
}

#define CP16(s, g) \
    asm volatile("cp.async.cg.shared.global [%0], [%1], 16;" :: "r"(s), "l"(g))
#define CPCOMMIT() asm volatile("cp.async.commit_group;" ::: "memory")
#define CPWAIT1() asm volatile("cp.async.wait_group 1;" ::: "memory")
#define CPWAIT0() asm volatile("cp.async.wait_group 0;" ::: "memory")

// ---------------------------------------------------------------------------
// K0: zero out_ctx + out_hid (atomicAdd targets).
// ---------------------------------------------------------------------------
__global__ __launch_bounds__(256) void zero_kernel(float4* __restrict__ p) {
    int i = blockIdx.x * 1024 + threadIdx.x;
#pragma unroll
    for (int u = 0; u < 4; u++) p[i + u * 256] = make_float4(0.f, 0.f, 0.f, 0.f);
}

// ---------------------------------------------------------------------------
// K1: qf = query @ Wq + bq   (128 x 1024, K=512)
// ---------------------------------------------------------------------------
__global__ __launch_bounds__(128) void qf_kernel(const float* __restrict__ query,
                                                 const float* __restrict__ Wq,
                                                 const float* __restrict__ bq) {
    int jc = blockIdx.x, tg = blockIdx.y, b = blockIdx.z;
    int j = jc * 128 + threadIdx.x;
    int t0 = tg * 8;
    __shared__ float q_s[8][HH];
    for (int i = threadIdx.x; i < 8 * HH; i += 128) {
        int r = i >> 9, c = i & (HH - 1);
        q_s[r][c] = query[(size_t)(b * TT + t0 + r) * HH + c];
    }
    __syncthreads();
    float acc[8];
    float bias = bq[j];
#pragma unroll
    for (int i = 0; i < 8; i++) acc[i] = bias;
#pragma unroll 8
    for (int k = 0; k < HH; k++) {
        float w = Wq[(size_t)k * H2 + j];
#pragma unroll
        for (int i = 0; i < 8; i++) acc[i] = fmaf(q_s[i][k], w, acc[i]);
    }
#pragma unroll
    for (int i = 0; i < 8; i++)
        g_qf[(size_t)(b * TT + t0 + i) * H2 + j] = acc[i];
}

// ---------------------------------------------------------------------------
// prep_A: states fp32 [4096,1024] -> gA_hi/gA_lo bf16 row-major.
// ---------------------------------------------------------------------------
__global__ __launch_bounds__(256) void prep_A(const float* __restrict__ A) {
    int idx = blockIdx.x * 256 + threadIdx.x;
#pragma unroll
    for (int q = 0; q < 4; q++) {
        int fid = idx * 4 + q;  // float4 index over [4096][1024]
        float4 vvv = *(const float4*)(A + (size_t)fid * 4);
        float h0 = __bfloat162float(__float2bfloat16_rn(vvv.x));
        float h1 = __bfloat162float(__float2bfloat16_rn(vvv.y));
        float h2 = __bfloat162float(__float2bfloat16_rn(vvv.z));
        float h3 = __bfloat162float(__float2bfloat16_rn(vvv.w));
        ull hi = (ull)pack2bf(h0, h1) | ((ull)pack2bf(h2, h3) << 32);
        ull lo = (ull)pack2bf(vvv.x - h0, vvv.y - h1) |
                 ((ull)pack2bf(vvv.z - h2, vvv.w - h3) << 32);
        *(ull*)(gA_hi + (size_t)fid * 8) = hi;
        *(ull*)(gA_lo + (size_t)fid * 8) = lo;
    }
}

// ---------------------------------------------------------------------------
// prep_B: Ws fp32 [K=1024, N=1024] -> gB_hi/gB_lo bf16 transposed [N][K].
// Block transposes 64x64 via smem. grid (kt=16, nb=16), 256 thr.
// ---------------------------------------------------------------------------
__global__ __launch_bounds__(256) void prep_B(const float* __restrict__ W) {
    __shared__ float tr[64][65];
    int k0 = blockIdx.x * 64, n0 = blockIdx.y * 64;
    int tid = threadIdx.x;
    int ki = tid >> 2, nq = (tid & 3) * 16;
#pragma unroll
    for (int j = 0; j < 4; j++) {
        float4 vv = *(const float4*)(W + (size_t)(k0 + ki) * H2 + n0 + nq + j * 4);
        tr[nq + j * 4 + 0][ki] = vv.x;
        tr[nq + j * 4 + 1][ki] = vv.y;
        tr[nq + j * 4 + 2][ki] = vv.z;
        tr[nq + j * 4 + 3][ki] = vv.w;
    }
    __syncthreads();
    int nr_l = tid >> 2, kq = (tid & 3) * 16;
    int n_g = n0 + nr_l;
#pragma unroll
    for (int j = 0; j < 4; j++) {
        int kr = kq + j * 4;
        float x0 = tr[nr_l][kr], x1 = tr[nr_l][kr + 1];
        float x2 = tr[nr_l][kr + 2], x3 = tr[nr_l][kr + 3];
        float h0 = __bfloat162float(__float2bfloat16_rn(x0));
        float h1 = __bfloat162float(__float2bfloat16_rn(x1));
        float h2 = __bfloat162float(__float2bfloat16_rn(x2));
        float h3 = __bfloat162float(__float2bfloat16_rn(x3));
        ull hi = (ull)pack2bf(h0, h1) | ((ull)pack2bf(h2, h3) << 32);
        ull lo = (ull)pack2bf(x0 - h0, x1 - h1) |
                 ((ull)pack2bf(x2 - h2, x3 - h3) << 32);
        size_t off = ((size_t)n_g * H2 + k0 + kr) * 2;
        *(ull*)(gB_hi + off) = hi;
        *(ull*)(gB_lo + off) = lo;
    }
}

// ---------------------------------------------------------------------------
// K2: sf = states @ Ws via mma.sync bf16 3-MMA split (Ah*Bh + Ah*Bl + Al*Bh).
// Block tile 256(M) x 128(N), 512 threads (16 warps, 4/SMSP), warp tile 64x32,
// K-chunks of 64, cp.async double buffer. 144B-padded rows -> conflict-free
// ldmatrix. grid (nt=8, mt=16) = 128 blocks = exactly 1 wave.
// ---------------------------------------------------------------------------
#define ROWB 144
#define A_TILE (256 * ROWB)               // 36864
#define B_TILE (128 * ROWB)               // 18432
#define STAGEB (2 * A_TILE + 2 * B_TILE)  // 110592
#define SMEM_MMA (2 * STAGEB)             // 221184

__device__ __forceinline__ void load_chunk(uint32_t sst, const char* gAh, const char* gAl,
                                           const char* gBh, const char* gBl,
                                           int c, int tid) {
    // A hi/lo: 256 rows x 8 quads = 2048 CP16 each, 4 iters of 512 threads
#pragma unroll
    for (int r = 0; r < 4; r++) {
        int i = r * 512 + tid;
        int row = i >> 3, quad = i & 7;
        uint32_t soff = row * ROWB + quad * 16;
        size_t goff = (size_t)row * 2048 + (size_t)c * 128 + quad * 16;
        CP16(sst + soff, gAh + goff);
        CP16(sst + A_TILE + soff, gAl + goff);
    }
    // B hi/lo: 128 rows x 8 quads = 1024 CP16 each, 2 iters
#pragma unroll
    for (int r = 0; r < 2; r++) {
        int i = r * 512 + tid;
        int row = i >> 3, quad = i & 7;
        uint32_t soff = row * ROWB + quad * 16;
        size_t goff = (size_t)row * 2048 + (size_t)c * 128 + quad * 16;
        CP16(sst + 2 * A_TILE + soff, gBh + goff);
        CP16(sst + 2 * A_TILE + B_TILE + soff, gBl + goff);
    }
}

__global__ __launch_bounds__(512, 1) void sf_mma() {
    extern __shared__ __align__(16) char sm[];
    uint32_t sbase = smem_u32(sm);
    int tid = threadIdx.x, lane = tid & 31, warp = tid >> 5;
    int nt = blockIdx.x, mt = blockIdx.y;
    int wm = warp >> 2, wn = warp & 3;  // warp tile: m = wm*64, n = wn*32

    const char* gAh = gA_hi + (size_t)(mt * 256) * 2048;
    const char* gAl = gA_lo + (size_t)(mt * 256) * 2048;
    const char* gBh = gB_hi + (size_t)(nt * 128) * 2048;
    const char* gBl = gB_lo + (size_t)(nt * 128) * 2048;

    float cacc[4][4][4] = {};

    load_chunk(sbase, gAh, gAl, gBh, gBl, 0, tid);
    CPCOMMIT();

#pragma unroll 1
    for (int c = 0; c < 16; c++) {
        int cur = c & 1;
        if (c + 1 < 16) {
            load_chunk(sbase + (cur ^ 1) * STAGEB, gAh, gAl, gBh, gBl, c + 1, tid);
            CPCOMMIT();
            CPWAIT1();
        } else {
            CPWAIT0();
        }
        __syncthreads();

        uint32_t sA_h = sbase + cur * STAGEB;
        uint32_t sA_l = sA_h + A_TILE;
        uint32_t sB_h = sA_h + 2 * A_TILE;
        uint32_t sB_l = sB_h + B_TILE;
        int r16 = lane & 15, hx = lane >> 4;

#pragma unroll
        for (int k16 = 0; k16 < 4; k16++) {
            int kb = k16 * 32 + hx * 16;
            uint32_t ah[4][4], bh[2][4];
#pragma unroll
            for (int mf = 0; mf < 4; mf++)
                LDSM_X4(ah[mf], sA_h + (wm * 64 + mf * 16 + r16) * ROWB + kb);
#pragma unroll
            for (int h = 0; h < 2; h++)
                LDSM_X4(bh[h], sB_h + (wn * 32 + h * 16 + r16) * ROWB + kb);
#pragma unroll
            for (int mf = 0; mf < 4; mf++)
#pragma unroll
                for (int nf = 0; nf < 4; nf++)
                    hmma(cacc[mf][nf], ah[mf], bh[nf >> 1][nf & 1], bh[nf >> 1][(nf & 1) + 2]);

            uint32_t bl[2][4];
#pragma unroll
            for (int h = 0; h < 2; h++)
                LDSM_X4(bl[h], sB_l + (wn * 32 + h * 16 + r16) * ROWB + kb);
#pragma unroll
            for (int mf = 0; mf < 4; mf++)
#pragma unroll
                for (int nf = 0; nf < 4; nf++)
                    hmma(cacc[mf][nf], ah[mf], bl[nf >> 1][nf & 1], bl[nf >> 1][(nf & 1) + 2]);

            uint32_t al[4][4];
#pragma unroll
            for (int mf = 0; mf < 4; mf++)
                LDSM_X4(al[mf], sA_l + (wm * 64 + mf * 16 + r16) * ROWB + kb);
#pragma unroll
            for (int mf = 0; mf < 4; mf++)
#pragma unroll
                for (int nf = 0; nf < 4; nf++)
                    hmma(cacc[mf][nf], al[mf], bh[nf >> 1][nf & 1], bh[nf >> 1][(nf & 1) + 2]);
        }
        __syncthreads();
    }

    // epilogue
    int tg = lane >> 2, tq = lane & 3;
#pragma unroll
    for (int mf = 0; mf < 4; mf++) {
#pragma unroll
        for (int nf = 0; nf < 4; nf++) {
            float* base = g_sf + (size_t)(mt * 256 + wm * 64 + mf * 16 + tg) * H2 +
                          nt * 128 + wn * 32 + nf * 8 + tq * 2;
            float2 v0 = {cacc[mf][nf][0], cacc[mf][nf][1]};
            float2 v1 = {cacc[mf][nf][2], cacc[mf][nf][3]};
            *(float2*)base = v0;
            *(float2*)(base + 8 * H2) = v1;
        }
    }
}

// ---------------------------------------------------------------------------
// K3a: raw alignments with qf reuse from smem (MUFU-floor bound).
// ---------------------------------------------------------------------------
__global__ __launch_bounds__(512, 1) void align_kernel(const float* __restrict__ v) {
    extern __shared__ float qf_s[];  // [TT][H2] = 128 KB
    int sc = blockIdx.x, b = blockIdx.y;
    int tid = threadIdx.x, lane = tid & 31, warp = tid >> 5;

    const float4* qsrc = (const float4*)(g_qf + (size_t)b * TT * H2);
    float4* qdst = (float4*)qf_s;
#pragma unroll
    for (int i = 0; i < 16; i++) qdst[tid + i * 512] = qsrc[tid + i * 512];

    float4 vr[8];
#pragma unroll
    for (int u = 0; u < 8; u++) vr[u] = *(const float4*)(v + u * 128 + lane * 4);
    __syncthreads();

#pragma unroll 1
    for (int si = 0; si < 2; si++) {
        int s = sc * 32 + warp * 2 + si;
        const float* sfrow = g_sf + ((size_t)(b * SS + s)) * H2;
        float4 sv[8];
#pragma unroll
        for (int u = 0; u < 8; u++)
            sv[u] = *(const float4*)(sfrow + u * 128 + lane * 4);

        float* ga = g_attn + (size_t)(b * TT) * SS + s;
#pragma unroll 1
        for (int t = 0; t < TT; t++) {
            const float* qrow = qf_s + t * H2;
            float a0 = 0.f, a1 = 0.f, a2 = 0.f, a3 = 0.f;
#pragma unroll
            for (int u = 0; u < 8; u++) {
                float4 q = *(const float4*)(qrow + u * 128 + lane * 4);
                a0 = fmaf(tanh_fast(q.x + sv[u].x), vr[u].x, a0);
                a1 = fmaf(tanh_fast(q.y + sv[u].y), vr[u].y, a1);
                a2 = fmaf(tanh_fast(q.z + sv[u].z), vr[u].z, a2);
                a3 = fmaf(tanh_fast(q.w + sv[u].w), vr[u].w, a3);
            }
            float acc = (a0 + a1) + (a2 + a3);
#pragma unroll
            for (int o = 16; o; o >>= 1) acc += __shfl_xor_sync(0xffffffffu, acc, o);
            if (lane == 0) ga[(size_t)t * SS] = acc;
        }
    }
}

// ---------------------------------------------------------------------------
// K3b: mask + softmax.
// ---------------------------------------------------------------------------
__global__ __launch_bounds__(256) void softmax_kernel(const int* __restrict__ mask,
                                                      float* __restrict__ out_att) {
    int t = blockIdx.x, b = blockIdx.y;
    int tid = threadIdx.x, lane = tid & 31, warp = tid >> 5;
    __shared__ float red[8];

    float* ga = g_attn + (size_t)(b * TT + t) * SS;
    float al[4];
#pragma unroll
    for (int i = 0; i < 4; i++) {
        int s = tid + i * 256;
        al[i] = mask[b * SS + s] ? ga[s] : -1e30f;
    }

    float m = fmaxf(fmaxf(al[0], al[1]), fmaxf(al[2], al[3]));
#pragma unroll
    for (int o = 16; o; o >>= 1) m = fmaxf(m, __shfl_xor_sync(0xffffffffu, m, o));
    if (lane == 0) red[warp] = m;
    __syncthreads();
    float mx = -1e30f;
#pragma unroll
    for (int i = 0; i < 8; i++) mx = fmaxf(mx, red[i]);

    float e[4];
    float ssum = 0.f;
#pragma unroll
    for (int i = 0; i < 4; i++) {
        e[i] = __expf(al[i] - mx);
        ssum += e[i];
    }
#pragma unroll
    for (int o = 16; o; o >>= 1) ssum += __shfl_xor_sync(0xffffffffu, ssum, o);
    __syncthreads();
    if (lane == 0) red[warp] = ssum;
    __syncthreads();
    float tot = 0.f;
#pragma unroll
    for (int i = 0; i < 8; i++) tot += red[i];
    float inv = 1.0f / tot;

    float* oa = out_att + (size_t)b * SS * TT + t;
#pragma unroll
    for (int i = 0; i < 4; i++) {
        int s = tid + i * 256;
        float w = e[i] * inv;
        ga[s] = w;
        oa[(size_t)s * TT] = w;
    }
}

// ---------------------------------------------------------------------------
// K4: context = attn @ states, split-S with atomicAdd epilogue.
// ---------------------------------------------------------------------------
__global__ __launch_bounds__(128) void ctx_kernel(const float* __restrict__ states,
                                                  float* __restrict__ out_ctx) {
    int dc = blockIdx.x, sc = blockIdx.y, b = blockIdx.z;
    int d = dc * 128 + threadIdx.x;
    int s0 = sc * 128;
    __shared__ float aw[TT][128];
    for (int i = threadIdx.x; i < TT * 128; i += 128) {
        int t = i >> 7, sl = i & 127;
        aw[t][sl] = g_attn[(size_t)(b * TT + t) * SS + s0 + sl];
    }
    __syncthreads();
    float acc[TT] = {};
    const float* sb = states + ((size_t)b * SS + s0) * H2 + d;
#pragma unroll 2
    for (int sl = 0; sl < 128; sl++) {
        float sv = sb[(size_t)sl * H2];
#pragma unroll
        for (int t = 0; t < TT; t++) acc[t] = fmaf(aw[t][sl], sv, acc[t]);
    }
#pragma unroll
    for (int t = 0; t < TT; t++)
        atomicAdd(&out_ctx[(size_t)(b * TT + t) * H2 + d], acc[t]);
}

// ---------------------------------------------------------------------------
// K5: attention_hidden = [context, query] @ Wc + bc, split-K with atomics.
// ---------------------------------------------------------------------------
__global__ __launch_bounds__(128) void hidden_kernel(const float* __restrict__ query,
                                                     const float* __restrict__ Wc,
                                                     const float* __restrict__ bc,
                                                     const float* __restrict__ ctx,
                                                     float* __restrict__ out_hid) {
    int hc = blockIdx.x, tg = blockIdx.y;
    int b = blockIdx.z >> 2, kc = blockIdx.z & 3;
    int h = hc * 128 + threadIdx.x;
    int t0 = tg * 8, k0 = kc * 384;
    __shared__ float cc[8][384];
    for (int i = threadIdx.x; i < 8 * 384; i += 128) {
        int r = i / 384, col = i - r * 384;
        int gk = k0 + col;
        cc[r][col] = (gk < H2)
                         ? ctx[(size_t)(b * TT + t0 + r) * H2 + gk]
                         : query[(size_t)(b * TT + t0 + r) * HH + gk - H2];
    }
    __syncthreads();
    float acc[8];
    float bias = (kc == 0) ? bc[h] : 0.f;
#pragma unroll
    for (int i = 0; i < 8; i++) acc[i] = bias;
#pragma unroll 4
    for (int k = 0; k < 384; k++) {
        float w = Wc[(size_t)(k0 + k) * HH + h];
#pragma unroll
        for (int i = 0; i < 8; i++) acc[i] = fmaf(cc[i][k], w, acc[i]);
    }
#pragma unroll
    for (int i = 0; i < 8; i++)
        atomicAdd(&out_hid[(size_t)(b * TT + t0 + i) * HH + h], acc[i]);
}

// ---------------------------------------------------------------------------
extern "C" void kernel_launch(void* const* d_in, const int* in_sizes, int n_in,
                              void* d_out, int out_size) {
    const float* query  = (const float*)d_in[0];
    const float* states = (const float*)d_in[1];
    const int*   mask   = (const int*)d_in[2];
    const float* Wq     = (const float*)d_in[3];
    const float* bq     = (const float*)d_in[4];
    const float* Ws     = (const float*)d_in[5];
    const float* v      = (const float*)d_in[6];
    const float* Wc     = (const float*)d_in[7];
    const float* bc     = (const float*)d_in[8];

    float* out_ctx = (float*)d_out;                  // (B,T,2H)
    float* out_hid = out_ctx + BB * TT * H2;         // (B,T,H)
    float* out_att = out_hid + BB * TT * HH;         // (B,S,T)

    static int attr_set = 0;
    if (!attr_set) {
        cudaFuncSetAttribute(align_kernel,
                             cudaFuncAttributeMaxDynamicSharedMemorySize,
                             TT * H2 * sizeof(float));
        cudaFuncSetAttribute(sf_mma,
                             cudaFuncAttributeMaxDynamicSharedMemorySize,
                             SMEM_MMA);
        attr_set = 1;
    }

    zero_kernel<<<48, 256>>>((float4*)d_out);
    qf_kernel<<<dim3(8, 4, 4), 128>>>(query, Wq, bq);
    prep_A<<<1024, 256>>>(states);
    prep_B<<<dim3(16, 16), 256>>>(Ws);
    sf_mma<<<dim3(8, 16), 512, SMEM_MMA>>>();
    align_kernel<<<dim3(32, BB), 512, TT * H2 * sizeof(float)>>>(v);
    softmax_kernel<<<dim3(TT, BB), 256>>>(mask, out_att);
    ctx_kernel<<<dim3(8, 8, 4), 128>>>(states, out_ctx);
    hidden_kernel<<<dim3(4, 4, 16), 128>>>(query, Wc, bc, out_ctx, out_hid);
}

// round 8
// speedup vs baseline: 2.9779x; 1.1011x over previous
#include <cuda_runtime.h>
#include <cuda_fp16.h>
#include <cstdint>

#define BB 4
#define TT 32
#define SS 1024
#define HH 512
#define H2 1024
#define H3 1536

typedef unsigned long long ull;

// ---------------------------------------------------------------------------
// Scratch (allocation-free: __device__ globals)
// ---------------------------------------------------------------------------
__device__ float g_qf[BB * TT * H2];          // 512 KB
__device__ float g_sf[(size_t)BB * SS * H2];  // 16 MB
__device__ float g_attn[BB * TT * SS];        // 512 KB
// fp16 operands, row-major K-major:
// gA_hi: [4096][1024] fp16 (states, hi only)
// gB_hi/gB_lo: [1024 n][1024 k] fp16 (Ws^T hi/lo split)
__device__ __align__(16) char gA_hi[8 << 20];
__device__ __align__(16) char gB_hi[2 << 20];
__device__ __align__(16) char gB_lo[2 << 20];

__device__ __forceinline__ float tanh_fast(float x) {
    float y;
    asm("tanh.approx.f32 %0, %1;" : "=f"(y) : "f"(x));
    return y;
}

__device__ __forceinline__ uint32_t smem_u32(const void* p) {
    uint32_t a;
    asm("{ .reg .u64 t; cvta.to.shared.u64 t, %1; cvt.u32.u64 %0, t; }" : "=r"(a) : "l"(p));
    return a;
}

__device__ __forceinline__ uint32_t pack2h(float a, float b) {
    __half2 h = __floats2half2_rn(a, b);
    return *(uint32_t*)&h;
}

// ---- baseline-PTX tensor ops (sm_80+) -------------------------------------
#define LDSM_X4(r, a) \
    asm volatile("ldmatrix.sync.aligned.m8n8.x4.shared.b16 {%0,%1,%2,%3}, [%4];" \
                 : "=r"((r)[0]), "=r"((r)[1]), "=r"((r)[2]), "=r"((r)[3]) : "r"(a))

__device__ __forceinline__ void hmma(float* c, const uint32_t* a, uint32_t b0, uint32_t b1) {
    asm volatile(
        "mma.sync.aligned.m16n8k16.row.col.f32.f16.f16.f32 "
        "{%0,%1,%2,%3}, {%4,%5,%6,%7}, {%8,%9}, {%0,%1,%2,%3};"
        : "+f"(c[0]), "+f"(c[1]), "+f"(c[2]), "+f"(c[3])
        : "r"(a[0]), "r"(a[1]), "r"(a[2]), "r"(a[3]), "r"(b0), "r"(b1));
}

#define CP16(s, g) \
    asm volatile("cp.async.cg.shared.global [%0], [%1], 16;" :: "r"(s), "l"(g))
#define CPCOMMIT() asm volatile("cp.async.commit_group;" ::: "memory")
#define CPWAIT1() asm volatile("cp.async.wait_group 1;" ::: "memory")
#define CPWAIT0() asm volatile("cp.async.wait_group 0;" ::: "memory")

// ---------------------------------------------------------------------------
// K0: zero out_ctx + out_hid (atomicAdd targets).
// ---------------------------------------------------------------------------
__global__ __launch_bounds__(256) void zero_kernel(float4* __restrict__ p) {
    int i = blockIdx.x * 1024 + threadIdx.x;
#pragma unroll
    for (int u = 0; u < 4; u++) p[i + u * 256] = make_float4(0.f, 0.f, 0.f, 0.f);
}

// ---------------------------------------------------------------------------
// K1: qf = query @ Wq + bq   (128 x 1024, K=512)
// ---------------------------------------------------------------------------
__global__ __launch_bounds__(128) void qf_kernel(const float* __restrict__ query,
                                                 const float* __restrict__ Wq,
                                                 const float* __restrict__ bq) {
    int jc = blockIdx.x, tg = blockIdx.y, b = blockIdx.z;
    int j = jc * 128 + threadIdx.x;
    int t0 = tg * 8;
    __shared__ float q_s[8][HH];
    for (int i = threadIdx.x; i < 8 * HH; i += 128) {
        int r = i >> 9, c = i & (HH - 1);
        q_s[r][c] = query[(size_t)(b * TT + t0 + r) * HH + c];
    }
    __syncthreads();
    float acc[8];
    float bias = bq[j];
#pragma unroll
    for (int i = 0; i < 8; i++) acc[i] = bias;
#pragma unroll 8
    for (int k = 0; k < HH; k++) {
        float w = Wq[(size_t)k * H2 + j];
#pragma unroll
        for (int i = 0; i < 8; i++) acc[i] = fmaf(q_s[i][k], w, acc[i]);
    }
#pragma unroll
    for (int i = 0; i < 8; i++)
        g_qf[(size_t)(b * TT + t0 + i) * H2 + j] = acc[i];
}

// ---------------------------------------------------------------------------
// prep_A: states fp32 [4096,1024] -> gA_hi fp16 row-major (hi only).
// ---------------------------------------------------------------------------
__global__ __launch_bounds__(256) void prep_A(const float* __restrict__ A) {
    int idx = blockIdx.x * 256 + threadIdx.x;
#pragma unroll
    for (int q = 0; q < 4; q++) {
        int fid = idx * 4 + q;  // float4 index over [4096][1024]
        float4 vvv = *(const float4*)(A + (size_t)fid * 4);
        ull hi = (ull)pack2h(vvv.x, vvv.y) | ((ull)pack2h(vvv.z, vvv.w) << 32);
        *(ull*)(gA_hi + (size_t)fid * 8) = hi;
    }
}

// ---------------------------------------------------------------------------
// prep_B: Ws fp32 [K=1024, N=1024] -> gB_hi/gB_lo fp16 transposed [N][K].
// Block transposes 64x64 via smem. grid (kt=16, nb=16), 256 thr.
// ---------------------------------------------------------------------------
__global__ __launch_bounds__(256) void prep_B(const float* __restrict__ W) {
    __shared__ float tr[64][65];
    int k0 = blockIdx.x * 64, n0 = blockIdx.y * 64;
    int tid = threadIdx.x;
    int ki = tid >> 2, nq = (tid & 3) * 16;
#pragma unroll
    for (int j = 0; j < 4; j++) {
        float4 vv = *(const float4*)(W + (size_t)(k0 + ki) * H2 + n0 + nq + j * 4);
        tr[nq + j * 4 + 0][ki] = vv.x;
        tr[nq + j * 4 + 1][ki] = vv.y;
        tr[nq + j * 4 + 2][ki] = vv.z;
        tr[nq + j * 4 + 3][ki] = vv.w;
    }
    __syncthreads();
    int nr_l = tid >> 2, kq = (tid & 3) * 16;
    int n_g = n0 + nr_l;
#pragma unroll
    for (int j = 0; j < 4; j++) {
        int kr = kq + j * 4;
        float x0 = tr[nr_l][kr], x1 = tr[nr_l][kr + 1];
        float x2 = tr[nr_l][kr + 2], x3 = tr[nr_l][kr + 3];
        float h0 = __half2float(__float2half_rn(x0));
        float h1 = __half2float(__float2half_rn(x1));
        float h2 = __half2float(__float2half_rn(x2));
        float h3 = __half2float(__float2half_rn(x3));
        ull hi = (ull)pack2h(h0, h1) | ((ull)pack2h(h2, h3) << 32);
        ull lo = (ull)pack2h(x0 - h0, x1 - h1) |
                 ((ull)pack2h(x2 - h2, x3 - h3) << 32);
        size_t off = ((size_t)n_g * H2 + k0 + kr) * 2;
        *(ull*)(gB_hi + off) = hi;
        *(ull*)(gB_lo + off) = lo;
    }
}

// ---------------------------------------------------------------------------
// K2: sf = states @ Ws via mma.sync fp16 2-MMA split (Ah*Bh + Ah*Bl).
// A fragments shared by both MMAs. Block tile 256(M) x 128(N), 512 threads,
// warp tile 64x32, K-chunks of 64, cp.async double buffer, 144B-padded rows.
// grid (nt=8, mt=16) = 128 blocks = 1 wave.
// ---------------------------------------------------------------------------
#define ROWB 144
#define A_TILE (256 * ROWB)           // 36864
#define B_TILE (128 * ROWB)           // 18432
#define STAGEB (A_TILE + 2 * B_TILE)  // 73728
#define SMEM_MMA (2 * STAGEB)         // 147456

__device__ __forceinline__ void load_chunk(uint32_t sst, const char* gAh,
                                           const char* gBh, const char* gBl,
                                           int c, int tid) {
    // A hi: 256 rows x 8 quads = 2048 CP16, 4 iters of 512 threads
#pragma unroll
    for (int r = 0; r < 4; r++) {
        int i = r * 512 + tid;
        int row = i >> 3, quad = i & 7;
        uint32_t soff = row * ROWB + quad * 16;
        size_t goff = (size_t)row * 2048 + (size_t)c * 128 + quad * 16;
        CP16(sst + soff, gAh + goff);
    }
    // B hi/lo: 128 rows x 8 quads = 1024 CP16 each, 2 iters
#pragma unroll
    for (int r = 0; r < 2; r++) {
        int i = r * 512 + tid;
        int row = i >> 3, quad = i & 7;
        uint32_t soff = row * ROWB + quad * 16;
        size_t goff = (size_t)row * 2048 + (size_t)c * 128 + quad * 16;
        CP16(sst + A_TILE + soff, gBh + goff);
        CP16(sst + A_TILE + B_TILE + soff, gBl + goff);
    }
}

__global__ __launch_bounds__(512, 1) void sf_mma() {
    extern __shared__ __align__(16) char sm[];
    uint32_t sbase = smem_u32(sm);
    int tid = threadIdx.x, lane = tid & 31, warp = tid >> 5;
    int nt = blockIdx.x, mt = blockIdx.y;
    int wm = warp >> 2, wn = warp & 3;  // warp tile: m = wm*64, n = wn*32

    const char* gAh = gA_hi + (size_t)(mt * 256) * 2048;
    const char* gBh = gB_hi + (size_t)(nt * 128) * 2048;
    const char* gBl = gB_lo + (size_t)(nt * 128) * 2048;

    float cacc[4][4][4] = {};

    load_chunk(sbase, gAh, gBh, gBl, 0, tid);
    CPCOMMIT();

#pragma unroll 1
    for (int c = 0; c < 16; c++) {
        int cur = c & 1;
        if (c + 1 < 16) {
            load_chunk(sbase + (cur ^ 1) * STAGEB, gAh, gBh, gBl, c + 1, tid);
            CPCOMMIT();
            CPWAIT1();
        } else {
            CPWAIT0();
        }
        __syncthreads();

        uint32_t sA_h = sbase + cur * STAGEB;
        uint32_t sB_h = sA_h + A_TILE;
        uint32_t sB_l = sB_h + B_TILE;
        int r16 = lane & 15, hx = lane >> 4;

#pragma unroll
        for (int k16 = 0; k16 < 4; k16++) {
            int kb = k16 * 32 + hx * 16;
            uint32_t ah[4][4], bh[2][4], bl[2][4];
#pragma unroll
            for (int mf = 0; mf < 4; mf++)
                LDSM_X4(ah[mf], sA_h + (wm * 64 + mf * 16 + r16) * ROWB + kb);
#pragma unroll
            for (int h = 0; h < 2; h++)
                LDSM_X4(bh[h], sB_h + (wn * 32 + h * 16 + r16) * ROWB + kb);
#pragma unroll
            for (int mf = 0; mf < 4; mf++)
#pragma unroll
                for (int nf = 0; nf < 4; nf++)
                    hmma(cacc[mf][nf], ah[mf], bh[nf >> 1][nf & 1], bh[nf >> 1][(nf & 1) + 2]);

#pragma unroll
            for (int h = 0; h < 2; h++)
                LDSM_X4(bl[h], sB_l + (wn * 32 + h * 16 + r16) * ROWB + kb);
#pragma unroll
            for (int mf = 0; mf < 4; mf++)
#pragma unroll
                for (int nf = 0; nf < 4; nf++)
                    hmma(cacc[mf][nf], ah[mf], bl[nf >> 1][nf & 1], bl[nf >> 1][(nf & 1) + 2]);
        }
        __syncthreads();
    }

    // epilogue
    int tg = lane >> 2, tq = lane & 3;
#pragma unroll
    for (int mf = 0; mf < 4; mf++) {
#pragma unroll
        for (int nf = 0; nf < 4; nf++) {
            float* base = g_sf + (size_t)(mt * 256 + wm * 64 + mf * 16 + tg) * H2 +
                          nt * 128 + wn * 32 + nf * 8 + tq * 2;
            float2 v0 = {cacc[mf][nf][0], cacc[mf][nf][1]};
            float2 v1 = {cacc[mf][nf][2], cacc[mf][nf][3]};
            *(float2*)base = v0;
            *(float2*)(base + 8 * H2) = v1;
        }
    }
}

// ---------------------------------------------------------------------------
// K3a: raw alignments with qf reuse from smem (MUFU-floor bound).
// ---------------------------------------------------------------------------
__global__ __launch_bounds__(512, 1) void align_kernel(const float* __restrict__ v) {
    extern __shared__ float qf_s[];  // [TT][H2] = 128 KB
    int sc = blockIdx.x, b = blockIdx.y;
    int tid = threadIdx.x, lane = tid & 31, warp = tid >> 5;

    const float4* qsrc = (const float4*)(g_qf + (size_t)b * TT * H2);
    float4* qdst = (float4*)qf_s;
#pragma unroll
    for (int i = 0; i < 16; i++) qdst[tid + i * 512] = qsrc[tid + i * 512];

    float4 vr[8];
#pragma unroll
    for (int u = 0; u < 8; u++) vr[u] = *(const float4*)(v + u * 128 + lane * 4);
    __syncthreads();

#pragma unroll 1
    for (int si = 0; si < 2; si++) {
        int s = sc * 32 + warp * 2 + si;
        const float* sfrow = g_sf + ((size_t)(b * SS + s)) * H2;
        float4 sv[8];
#pragma unroll
        for (int u = 0; u < 8; u++)
            sv[u] = *(const float4*)(sfrow + u * 128 + lane * 4);

        float* ga = g_attn + (size_t)(b * TT) * SS + s;
#pragma unroll 1
        for (int t = 0; t < TT; t++) {
            const float* qrow = qf_s + t * H2;
            float a0 = 0.f, a1 = 0.f, a2 = 0.f, a3 = 0.f;
#pragma unroll
            for (int u = 0; u < 8; u++) {
                float4 q = *(const float4*)(qrow + u * 128 + lane * 4);
                a0 = fmaf(tanh_fast(q.x + sv[u].x), vr[u].x, a0);
                a1 = fmaf(tanh_fast(q.y + sv[u].y), vr[u].y, a1);
                a2 = fmaf(tanh_fast(q.z + sv[u].z), vr[u].z, a2);
                a3 = fmaf(tanh_fast(q.w + sv[u].w), vr[u].w, a3);
            }
            float acc = (a0 + a1) + (a2 + a3);
#pragma unroll
            for (int o = 16; o; o >>= 1) acc += __shfl_xor_sync(0xffffffffu, acc, o);
            if (lane == 0) ga[(size_t)t * SS] = acc;
        }
    }
}

// ---------------------------------------------------------------------------
// K3b: mask + softmax.
// ---------------------------------------------------------------------------
__global__ __launch_bounds__(256) void softmax_kernel(const int* __restrict__ mask,
                                                      float* __restrict__ out_att) {
    int t = blockIdx.x, b = blockIdx.y;
    int tid = threadIdx.x, lane = tid & 31, warp = tid >> 5;
    __shared__ float red[8];

    float* ga = g_attn + (size_t)(b * TT + t) * SS;
    float al[4];
#pragma unroll
    for (int i = 0; i < 4; i++) {
        int s = tid + i * 256;
        al[i] = mask[b * SS + s] ? ga[s] : -1e30f;
    }

    float m = fmaxf(fmaxf(al[0], al[1]), fmaxf(al[2], al[3]));
#pragma unroll
    for (int o = 16; o; o >>= 1) m = fmaxf(m, __shfl_xor_sync(0xffffffffu, m, o));
    if (lane == 0) red[warp] = m;
    __syncthreads();
    float mx = -1e30f;
#pragma unroll
    for (int i = 0; i < 8; i++) mx = fmaxf(mx, red[i]);

    float e[4];
    float ssum = 0.f;
#pragma unroll
    for (int i = 0; i < 4; i++) {
        e[i] = __expf(al[i] - mx);
        ssum += e[i];
    }
#pragma unroll
    for (int o = 16; o; o >>= 1) ssum += __shfl_xor_sync(0xffffffffu, ssum, o);
    __syncthreads();
    if (lane == 0) red[warp] = ssum;
    __syncthreads();
    float tot = 0.f;
#pragma unroll
    for (int i = 0; i < 8; i++) tot += red[i];
    float inv = 1.0f / tot;

    float* oa = out_att + (size_t)b * SS * TT + t;
#pragma unroll
    for (int i = 0; i < 4; i++) {
        int s = tid + i * 256;
        float w = e[i] * inv;
        ga[s] = w;
        oa[(size_t)s * TT] = w;
    }
}

// ---------------------------------------------------------------------------
// K4: context = attn @ states, split-S with atomicAdd epilogue.
// ---------------------------------------------------------------------------
__global__ __launch_bounds__(128) void ctx_kernel(const float* __restrict__ states,
                                                  float* __restrict__ out_ctx) {
    int dc = blockIdx.x, sc = blockIdx.y, b = blockIdx.z;
    int d = dc * 128 + threadIdx.x;
    int s0 = sc * 128;
    __shared__ float aw[TT][128];
    for (int i = threadIdx.x; i < TT * 128; i += 128) {
        int t = i >> 7, sl = i & 127;
        aw[t][sl] = g_attn[(size_t)(b * TT + t) * SS + s0 + sl];
    }
    __syncthreads();
    float acc[TT] = {};
    const float* sb = states + ((size_t)b * SS + s0) * H2 + d;
#pragma unroll 2
    for (int sl = 0; sl < 128; sl++) {
        float sv = sb[(size_t)sl * H2];
#pragma unroll
        for (int t = 0; t < TT; t++) acc[t] = fmaf(aw[t][sl], sv, acc[t]);
    }
#pragma unroll
    for (int t = 0; t < TT; t++)
        atomicAdd(&out_ctx[(size_t)(b * TT + t) * H2 + d], acc[t]);
}

// ---------------------------------------------------------------------------
// K5: attention_hidden = [context, query] @ Wc + bc, split-K with atomics.
// ---------------------------------------------------------------------------
__global__ __launch_bounds__(128) void hidden_kernel(const float* __restrict__ query,
                                                     const float* __restrict__ Wc,
                                                     const float* __restrict__ bc,
                                                     const float* __restrict__ ctx,
                                                     float* __restrict__ out_hid) {
    int hc = blockIdx.x, tg = blockIdx.y;
    int b = blockIdx.z >> 2, kc = blockIdx.z & 3;
    int h = hc * 128 + threadIdx.x;
    int t0 = tg * 8, k0 = kc * 384;
    __shared__ float cc[8][384];
    for (int i = threadIdx.x; i < 8 * 384; i += 128) {
        int r = i / 384, col = i - r * 384;
        int gk = k0 + col;
        cc[r][col] = (gk < H2)
                         ? ctx[(size_t)(b * TT + t0 + r) * H2 + gk]
                         : query[(size_t)(b * TT + t0 + r) * HH + gk - H2];
    }
    __syncthreads();
    float acc[8];
    float bias = (kc == 0) ? bc[h] : 0.f;
#pragma unroll
    for (int i = 0; i < 8; i++) acc[i] = bias;
#pragma unroll 4
    for (int k = 0; k < 384; k++) {
        float w = Wc[(size_t)(k0 + k) * HH + h];
#pragma unroll
        for (int i = 0; i < 8; i++) acc[i] = fmaf(cc[i][k], w, acc[i]);
    }
#pragma unroll
    for (int i = 0; i < 8; i++)
        atomicAdd(&out_hid[(size_t)(b * TT + t0 + i) * HH + h], acc[i]);
}

// ---------------------------------------------------------------------------
extern "C" void kernel_launch(void* const* d_in, const int* in_sizes, int n_in,
                              void* d_out, int out_size) {
    const float* query  = (const float*)d_in[0];
    const float* states = (const float*)d_in[1];
    const int*   mask   = (const int*)d_in[2];
    const float* Wq     = (const float*)d_in[3];
    const float* bq     = (const float*)d_in[4];
    const float* Ws     = (const float*)d_in[5];
    const float* v      = (const float*)d_in[6];
    const float* Wc     = (const float*)d_in[7];
    const float* bc     = (const float*)d_in[8];

    float* out_ctx = (float*)d_out;                  // (B,T,2H)
    float* out_hid = out_ctx + BB * TT * H2;         // (B,T,H)
    float* out_att = out_hid + BB * TT * HH;         // (B,S,T)

    static cudaStream_t s1 = nullptr, s2 = nullptr;
    static cudaEvent_t ef, e1, e2;
    if (!s1) {
        cudaStreamCreateWithFlags(&s1, cudaStreamNonBlocking);
        cudaStreamCreateWithFlags(&s2, cudaStreamNonBlocking);
        cudaEventCreateWithFlags(&ef, cudaEventDisableTiming);
        cudaEventCreateWithFlags(&e1, cudaEventDisableTiming);
        cudaEventCreateWithFlags(&e2, cudaEventDisableTiming);
        cudaFuncSetAttribute(align_kernel,
                             cudaFuncAttributeMaxDynamicSharedMemorySize,
                             TT * H2 * sizeof(float));
        cudaFuncSetAttribute(sf_mma,
                             cudaFuncAttributeMaxDynamicSharedMemorySize,
                             SMEM_MMA);
    }

    // fork
    cudaEventRecord(ef, 0);
    cudaStreamWaitEvent(s1, ef, 0);
    cudaStreamWaitEvent(s2, ef, 0);

    prep_B<<<dim3(16, 16), 256, 0, s1>>>(Ws);
    cudaEventRecord(e1, s1);

    zero_kernel<<<48, 256, 0, s2>>>((float4*)d_out);
    qf_kernel<<<dim3(8, 4, 4), 128, 0, s2>>>(query, Wq, bq);
    cudaEventRecord(e2, s2);

    prep_A<<<1024, 256>>>(states);
    cudaStreamWaitEvent(0, e1, 0);  // prep_B done
    sf_mma<<<dim3(8, 16), 512, SMEM_MMA>>>();
    cudaStreamWaitEvent(0, e2, 0);  // qf + zero done
    align_kernel<<<dim3(32, BB), 512, TT * H2 * sizeof(float)>>>(v);
    softmax_kernel<<<dim3(TT, BB), 256>>>(mask, out_att);
    ctx_kernel<<<dim3(8, 8, 4), 128>>>(states, out_ctx);
    hidden_kernel<<<dim3(4, 4, 16), 128>>>(query, Wc, bc, out_ctx, out_hid);
}

// round 9
// speedup vs baseline: 3.6662x; 1.2312x over previous
#include <cuda_runtime.h>
#include <cuda_fp16.h>
#include <cstdint>

#define BB 4
#define TT 32
#define SS 1024
#define HH 512
#define H2 1024
#define H3 1536

typedef unsigned long long ull;

// ---------------------------------------------------------------------------
// Scratch (allocation-free: __device__ globals)
// ---------------------------------------------------------------------------
__device__ float g_qf[BB * TT * H2];          // 512 KB
__device__ float g_sf[(size_t)BB * SS * H2];  // 16 MB
__device__ float g_attn[BB * TT * SS];        // 512 KB
// fp16 operands, row-major K-major:
// gA_hi: [4096][1024] fp16 (states, hi only)
// gB_hi/gB_lo: [1024 n][1024 k] fp16 (Ws^T hi/lo split)
__device__ __align__(16) char gA_hi[8 << 20];
__device__ __align__(16) char gB_hi[2 << 20];
__device__ __align__(16) char gB_lo[2 << 20];

__device__ __forceinline__ float tanh_fast(float x) {
    float y;
    asm("tanh.approx.f32 %0, %1;" : "=f"(y) : "f"(x));
    return y;
}

__device__ __forceinline__ uint32_t smem_u32(const void* p) {
    uint32_t a;
    asm("{ .reg .u64 t; cvta.to.shared.u64 t, %1; cvt.u32.u64 %0, t; }" : "=r"(a) : "l"(p));
    return a;
}

__device__ __forceinline__ uint32_t pack2h(float a, float b) {
    __half2 h = __floats2half2_rn(a, b);
    return *(uint32_t*)&h;
}

// ---- baseline-PTX tensor ops (sm_80+) -------------------------------------
#define LDSM_X4(r, a) \
    asm volatile("ldmatrix.sync.aligned.m8n8.x4.shared.b16 {%0,%1,%2,%3}, [%4];" \
                 : "=r"((r)[0]), "=r"((r)[1]), "=r"((r)[2]), "=r"((r)[3]) : "r"(a))

__device__ __forceinline__ void hmma(float* c, const uint32_t* a, uint32_t b0, uint32_t b1) {
    asm volatile(
        "mma.sync.aligned.m16n8k16.row.col.f32.f16.f16.f32 "
        "{%0,%1,%2,%3}, {%4,%5,%6,%7}, {%8,%9}, {%0,%1,%2,%3};"
        : "+f"(c[0]), "+f"(c[1]), "+f"(c[2]), "+f"(c[3])
        : "r"(a[0]), "r"(a[1]), "r"(a[2]), "r"(a[3]), "r"(b0), "r"(b1));
}

#define CP16(s, g) \
    asm volatile("cp.async.cg.shared.global [%0], [%1], 16;" :: "r"(s), "l"(g))
#define CPCOMMIT() asm volatile("cp.async.commit_group;" ::: "memory")
#define CPWAIT1() asm volatile("cp.async.wait_group 1;" ::: "memory")
#define CPWAIT0() asm volatile("cp.async.wait_group 0;" ::: "memory")

// ---------------------------------------------------------------------------
// K0: zero out_ctx only (atomicAdd target). 131072 floats = 32768 float4.
// ---------------------------------------------------------------------------
__global__ __launch_bounds__(256) void zero_kernel(float4* __restrict__ p) {
    int i = blockIdx.x * 1024 + threadIdx.x;
#pragma unroll
    for (int u = 0; u < 4; u++) p[i + u * 256] = make_float4(0.f, 0.f, 0.f, 0.f);
}

// ---------------------------------------------------------------------------
// K1: qf = query @ Wq + bq   (128 x 1024, K=512)
// ---------------------------------------------------------------------------
__global__ __launch_bounds__(128) void qf_kernel(const float* __restrict__ query,
                                                 const float* __restrict__ Wq,
                                                 const float* __restrict__ bq) {
    int jc = blockIdx.x, tg = blockIdx.y, b = blockIdx.z;
    int j = jc * 128 + threadIdx.x;
    int t0 = tg * 8;
    __shared__ float q_s[8][HH];
    for (int i = threadIdx.x; i < 8 * HH; i += 128) {
        int r = i >> 9, c = i & (HH - 1);
        q_s[r][c] = query[(size_t)(b * TT + t0 + r) * HH + c];
    }
    __syncthreads();
    float acc[8];
    float bias = bq[j];
#pragma unroll
    for (int i = 0; i < 8; i++) acc[i] = bias;
#pragma unroll 8
    for (int k = 0; k < HH; k++) {
        float w = Wq[(size_t)k * H2 + j];
#pragma unroll
        for (int i = 0; i < 8; i++) acc[i] = fmaf(q_s[i][k], w, acc[i]);
    }
#pragma unroll
    for (int i = 0; i < 8; i++)
        g_qf[(size_t)(b * TT + t0 + i) * H2 + j] = acc[i];
}

// ---------------------------------------------------------------------------
// K1b: hid_q = query @ Wc[1024:1536] + bc  -> writes out_hid directly.
// grid (hc=4, tg=4, b=4), 128 thr.
// ---------------------------------------------------------------------------
__global__ __launch_bounds__(128) void hid_q_kernel(const float* __restrict__ query,
                                                    const float* __restrict__ Wc,
                                                    const float* __restrict__ bc,
                                                    float* __restrict__ out_hid) {
    int hc = blockIdx.x, tg = blockIdx.y, b = blockIdx.z;
    int h = hc * 128 + threadIdx.x;
    int t0 = tg * 8;
    __shared__ float q_s[8][HH];
    for (int i = threadIdx.x; i < 8 * HH; i += 128) {
        int r = i >> 9, c = i & (HH - 1);
        q_s[r][c] = query[(size_t)(b * TT + t0 + r) * HH + c];
    }
    __syncthreads();
    float acc[8];
    float bias = bc[h];
#pragma unroll
    for (int i = 0; i < 8; i++) acc[i] = bias;
#pragma unroll 8
    for (int k = 0; k < HH; k++) {
        float w = Wc[(size_t)(H2 + k) * HH + h];
#pragma unroll
        for (int i = 0; i < 8; i++) acc[i] = fmaf(q_s[i][k], w, acc[i]);
    }
#pragma unroll
    for (int i = 0; i < 8; i++)
        out_hid[(size_t)(b * TT + t0 + i) * HH + h] = acc[i];
}

// ---------------------------------------------------------------------------
// prep_A: states fp32 [4096,1024] -> gA_hi fp16 row-major (hi only).
// ---------------------------------------------------------------------------
__global__ __launch_bounds__(256) void prep_A(const float* __restrict__ A) {
    int idx = blockIdx.x * 256 + threadIdx.x;
#pragma unroll
    for (int q = 0; q < 4; q++) {
        int fid = idx * 4 + q;
        float4 vvv = *(const float4*)(A + (size_t)fid * 4);
        ull hi = (ull)pack2h(vvv.x, vvv.y) | ((ull)pack2h(vvv.z, vvv.w) << 32);
        *(ull*)(gA_hi + (size_t)fid * 8) = hi;
    }
}

// ---------------------------------------------------------------------------
// prep_B: Ws fp32 [K=1024, N=1024] -> gB_hi/gB_lo fp16 transposed [N][K].
// ---------------------------------------------------------------------------
__global__ __launch_bounds__(256) void prep_B(const float* __restrict__ W) {
    __shared__ float tr[64][65];
    int k0 = blockIdx.x * 64, n0 = blockIdx.y * 64;
    int tid = threadIdx.x;
    int ki = tid >> 2, nq = (tid & 3) * 16;
#pragma unroll
    for (int j = 0; j < 4; j++) {
        float4 vv = *(const float4*)(W + (size_t)(k0 + ki) * H2 + n0 + nq + j * 4);
        tr[nq + j * 4 + 0][ki] = vv.x;
        tr[nq + j * 4 + 1][ki] = vv.y;
        tr[nq + j * 4 + 2][ki] = vv.z;
        tr[nq + j * 4 + 3][ki] = vv.w;
    }
    __syncthreads();
    int nr_l = tid >> 2, kq = (tid & 3) * 16;
    int n_g = n0 + nr_l;
#pragma unroll
    for (int j = 0; j < 4; j++) {
        int kr = kq + j * 4;
        float x0 = tr[nr_l][kr], x1 = tr[nr_l][kr + 1];
        float x2 = tr[nr_l][kr + 2], x3 = tr[nr_l][kr + 3];
        float h0 = __half2float(__float2half_rn(x0));
        float h1 = __half2float(__float2half_rn(x1));
        float h2 = __half2float(__float2half_rn(x2));
        float h3 = __half2float(__float2half_rn(x3));
        ull hi = (ull)pack2h(h0, h1) | ((ull)pack2h(h2, h3) << 32);
        ull lo = (ull)pack2h(x0 - h0, x1 - h1) |
                 ((ull)pack2h(x2 - h2, x3 - h3) << 32);
        size_t off = ((size_t)n_g * H2 + k0 + kr) * 2;
        *(ull*)(gB_hi + off) = hi;
        *(ull*)(gB_lo + off) = lo;
    }
}

// ---------------------------------------------------------------------------
// K2: sf = states @ Ws via mma.sync fp16 2-MMA split (Ah*Bh + Ah*Bl).
// Block tile 256(M) x 64(N), 512 threads (16 warps), warp tile 64x16
// (warp grid 4m x 4n). grid (nt=16, mt=16) = 256 blocks = exactly 2 waves.
// ~80 regs/thread (no spills). K-chunks 64, cp.async double buffer, 144B rows.
// ---------------------------------------------------------------------------
#define ROWB 144
#define A_TILE (256 * ROWB)           // 36864
#define B_TILE (64 * ROWB)            // 9216
#define STAGEB (A_TILE + 2 * B_TILE)  // 55296
#define SMEM_MMA (2 * STAGEB)         // 110592

__device__ __forceinline__ void load_chunk(uint32_t sst, const char* gAh,
                                           const char* gBh, const char* gBl,
                                           int c, int tid) {
    // A: 256 rows x 8 quads = 2048 CP16, 4 iters of 512 threads
#pragma unroll
    for (int r = 0; r < 4; r++) {
        int i = r * 512 + tid;
        int row = i >> 3, quad = i & 7;
        uint32_t soff = row * ROWB + quad * 16;
        size_t goff = (size_t)row * 2048 + (size_t)c * 128 + quad * 16;
        CP16(sst + soff, gAh + goff);
    }
    // B hi/lo: 64 rows x 8 quads = 512 CP16 each, 1 iter
    {
        int row = tid >> 3, quad = tid & 7;
        uint32_t soff = row * ROWB + quad * 16;
        size_t goff = (size_t)row * 2048 + (size_t)c * 128 + quad * 16;
        CP16(sst + A_TILE + soff, gBh + goff);
        CP16(sst + A_TILE + B_TILE + soff, gBl + goff);
    }
}

__global__ __launch_bounds__(512, 1) void sf_mma() {
    extern __shared__ __align__(16) char sm[];
    uint32_t sbase = smem_u32(sm);
    int tid = threadIdx.x, lane = tid & 31, warp = tid >> 5;
    int nt = blockIdx.x, mt = blockIdx.y;
    int wm = warp >> 2, wn = warp & 3;  // warp tile: m = wm*64, n = wn*16

    const char* gAh = gA_hi + (size_t)(mt * 256) * 2048;
    const char* gBh = gB_hi + (size_t)(nt * 64) * 2048;
    const char* gBl = gB_lo + (size_t)(nt * 64) * 2048;

    float cacc[4][2][4] = {};

    load_chunk(sbase, gAh, gBh, gBl, 0, tid);
    CPCOMMIT();

#pragma unroll 1
    for (int c = 0; c < 16; c++) {
        int cur = c & 1;
        if (c + 1 < 16) {
            load_chunk(sbase + (cur ^ 1) * STAGEB, gAh, gBh, gBl, c + 1, tid);
            CPCOMMIT();
            CPWAIT1();
        } else {
            CPWAIT0();
        }
        __syncthreads();

        uint32_t sA = sbase + cur * STAGEB;
        uint32_t sB_h = sA + A_TILE;
        uint32_t sB_l = sB_h + B_TILE;
        int r16 = lane & 15, hx = lane >> 4;

#pragma unroll
        for (int k16 = 0; k16 < 4; k16++) {
            int kb = k16 * 32 + hx * 16;
            uint32_t ah[4][4];
#pragma unroll
            for (int mf = 0; mf < 4; mf++)
                LDSM_X4(ah[mf], sA + (wm * 64 + mf * 16 + r16) * ROWB + kb);
            {
                uint32_t bh[4];
                LDSM_X4(bh, sB_h + (wn * 16 + r16) * ROWB + kb);
#pragma unroll
                for (int mf = 0; mf < 4; mf++)
#pragma unroll
                    for (int nf = 0; nf < 2; nf++)
                        hmma(cacc[mf][nf], ah[mf], bh[nf], bh[nf + 2]);
            }
            {
                uint32_t bl[4];
                LDSM_X4(bl, sB_l + (wn * 16 + r16) * ROWB + kb);
#pragma unroll
                for (int mf = 0; mf < 4; mf++)
#pragma unroll
                    for (int nf = 0; nf < 2; nf++)
                        hmma(cacc[mf][nf], ah[mf], bl[nf], bl[nf + 2]);
            }
        }
        __syncthreads();
    }

    // epilogue
    int tg = lane >> 2, tq = lane & 3;
#pragma unroll
    for (int mf = 0; mf < 4; mf++) {
#pragma unroll
        for (int nf = 0; nf < 2; nf++) {
            float* base = g_sf + (size_t)(mt * 256 + wm * 64 + mf * 16 + tg) * H2 +
                          nt * 64 + wn * 16 + nf * 8 + tq * 2;
            float2 v0 = {cacc[mf][nf][0], cacc[mf][nf][1]};
            float2 v1 = {cacc[mf][nf][2], cacc[mf][nf][3]};
            *(float2*)base = v0;
            *(float2*)(base + 8 * H2) = v1;
        }
    }
}

// ---------------------------------------------------------------------------
// K3a: raw alignments. Block (sc, b), 512 thr, qf[b] in smem. Warp handles
// 2 s-rows; BOTH s preloaded in regs so each q LDS.128 feeds 8 tanh-FMAs.
// v read via global (L1-resident).
// ---------------------------------------------------------------------------
__global__ __launch_bounds__(512, 1) void align_kernel(const float* __restrict__ v) {
    extern __shared__ float qf_s[];  // [TT][H2] = 128 KB
    int sc = blockIdx.x, b = blockIdx.y;
    int tid = threadIdx.x, lane = tid & 31, warp = tid >> 5;

    const float4* qsrc = (const float4*)(g_qf + (size_t)b * TT * H2);
    float4* qdst = (float4*)qf_s;
#pragma unroll
    for (int i = 0; i < 16; i++) qdst[tid + i * 512] = qsrc[tid + i * 512];

    int s0 = sc * 32 + warp * 2;
    float4 sv[2][8];
#pragma unroll
    for (int si = 0; si < 2; si++) {
        const float* sfrow = g_sf + ((size_t)(b * SS + s0 + si)) * H2;
#pragma unroll
        for (int u = 0; u < 8; u++)
            sv[si][u] = *(const float4*)(sfrow + u * 128 + lane * 4);
    }
    __syncthreads();

    float* ga = g_attn + (size_t)(b * TT) * SS + s0;
#pragma unroll 1
    for (int t = 0; t < TT; t++) {
        const float* qrow = qf_s + t * H2;
        float a00 = 0.f, a01 = 0.f, a10 = 0.f, a11 = 0.f;
#pragma unroll
        for (int u = 0; u < 8; u++) {
            float4 q = *(const float4*)(qrow + u * 128 + lane * 4);
            float4 vv = __ldg((const float4*)(v + u * 128 + lane * 4));
            a00 = fmaf(tanh_fast(q.x + sv[0][u].x), vv.x, a00);
            a01 = fmaf(tanh_fast(q.y + sv[0][u].y), vv.y, a01);
            a00 = fmaf(tanh_fast(q.z + sv[0][u].z), vv.z, a00);
            a01 = fmaf(tanh_fast(q.w + sv[0][u].w), vv.w, a01);
            a10 = fmaf(tanh_fast(q.x + sv[1][u].x), vv.x, a10);
            a11 = fmaf(tanh_fast(q.y + sv[1][u].y), vv.y, a11);
            a10 = fmaf(tanh_fast(q.z + sv[1][u].z), vv.z, a10);
            a11 = fmaf(tanh_fast(q.w + sv[1][u].w), vv.w, a11);
        }
        float acc0 = a00 + a01;
        float acc1 = a10 + a11;
#pragma unroll
        for (int o = 16; o; o >>= 1) {
            acc0 += __shfl_xor_sync(0xffffffffu, acc0, o);
            acc1 += __shfl_xor_sync(0xffffffffu, acc1, o);
        }
        if (lane == 0) {
            ga[(size_t)t * SS] = acc0;
            ga[(size_t)t * SS + 1] = acc1;
        }
    }
}

// ---------------------------------------------------------------------------
// K3b: mask + softmax.
// ---------------------------------------------------------------------------
__global__ __launch_bounds__(256) void softmax_kernel(const int* __restrict__ mask,
                                                      float* __restrict__ out_att) {
    int t = blockIdx.x, b = blockIdx.y;
    int tid = threadIdx.x, lane = tid & 31, warp = tid >> 5;
    __shared__ float red[8];

    float* ga = g_attn + (size_t)(b * TT + t) * SS;
    float al[4];
#pragma unroll
    for (int i = 0; i < 4; i++) {
        int s = tid + i * 256;
        al[i] = mask[b * SS + s] ? ga[s] : -1e30f;
    }

    float m = fmaxf(fmaxf(al[0], al[1]), fmaxf(al[2], al[3]));
#pragma unroll
    for (int o = 16; o; o >>= 1) m = fmaxf(m, __shfl_xor_sync(0xffffffffu, m, o));
    if (lane == 0) red[warp] = m;
    __syncthreads();
    float mx = -1e30f;
#pragma unroll
    for (int i = 0; i < 8; i++) mx = fmaxf(mx, red[i]);

    float e[4];
    float ssum = 0.f;
#pragma unroll
    for (int i = 0; i < 4; i++) {
        e[i] = __expf(al[i] - mx);
        ssum += e[i];
    }
#pragma unroll
    for (int o = 16; o; o >>= 1) ssum += __shfl_xor_sync(0xffffffffu, ssum, o);
    __syncthreads();
    if (lane == 0) red[warp] = ssum;
    __syncthreads();
    float tot = 0.f;
#pragma unroll
    for (int i = 0; i < 8; i++) tot += red[i];
    float inv = 1.0f / tot;

    float* oa = out_att + (size_t)b * SS * TT + t;
#pragma unroll
    for (int i = 0; i < 4; i++) {
        int s = tid + i * 256;
        float w = e[i] * inv;
        ga[s] = w;
        oa[(size_t)s * TT] = w;
    }
}

// ---------------------------------------------------------------------------
// K4: context = attn @ states, split-S (64) with atomicAdd epilogue.
// grid (dc=8, sc=16, b=4) = 512 blocks, 128 thr.
// ---------------------------------------------------------------------------
__global__ __launch_bounds__(128) void ctx_kernel(const float* __restrict__ states,
                                                  float* __restrict__ out_ctx) {
    int dc = blockIdx.x, sc = blockIdx.y, b = blockIdx.z;
    int d = dc * 128 + threadIdx.x;
    int s0 = sc * 64;
    __shared__ float aw[TT][64];
    for (int i = threadIdx.x; i < TT * 64; i += 128) {
        int t = i >> 6, sl = i & 63;
        aw[t][sl] = g_attn[(size_t)(b * TT + t) * SS + s0 + sl];
    }
    __syncthreads();
    float acc[TT] = {};
    const float* sb = states + ((size_t)b * SS + s0) * H2 + d;
#pragma unroll 4
    for (int sl = 0; sl < 64; sl++) {
        float sv = sb[(size_t)sl * H2];
#pragma unroll
        for (int t = 0; t < TT; t++) acc[t] = fmaf(aw[t][sl], sv, acc[t]);
    }
#pragma unroll
    for (int t = 0; t < TT; t++)
        atomicAdd(&out_ctx[(size_t)(b * TT + t) * H2 + d], acc[t]);
}

// ---------------------------------------------------------------------------
// K5: attention_hidden += context @ Wc[0:1024] (query part done by hid_q).
// Split-K: grid (hc=4, tg=4, b*8+kc=32) = 512 blocks, 128 thr, K-chunk 128.
// ---------------------------------------------------------------------------
__global__ __launch_bounds__(128) void hidden_kernel(const float* __restrict__ Wc,
                                                     const float* __restrict__ ctx,
                                                     float* __restrict__ out_hid) {
    int hc = blockIdx.x, tg = blockIdx.y;
    int b = blockIdx.z >> 3, kc = blockIdx.z & 7;
    int h = hc * 128 + threadIdx.x;
    int t0 = tg * 8, k0 = kc * 128;
    __shared__ float cc[8][128];
    for (int i = threadIdx.x; i < 8 * 128; i += 128) {
        int r = i >> 7, col = i & 127;
        cc[r][col] = ctx[(size_t)(b * TT + t0 + r) * H2 + k0 + col];
    }
    __syncthreads();
    float acc[8] = {};
#pragma unroll 4
    for (int k = 0; k < 128; k++) {
        float w = Wc[(size_t)(k0 + k) * HH + h];
#pragma unroll
        for (int i = 0; i < 8; i++) acc[i] = fmaf(cc[i][k], w, acc[i]);
    }
#pragma unroll
    for (int i = 0; i < 8; i++)
        atomicAdd(&out_hid[(size_t)(b * TT + t0 + i) * HH + h], acc[i]);
}

// ---------------------------------------------------------------------------
extern "C" void kernel_launch(void* const* d_in, const int* in_sizes, int n_in,
                              void* d_out, int out_size) {
    const float* query  = (const float*)d_in[0];
    const float* states = (const float*)d_in[1];
    const int*   mask   = (const int*)d_in[2];
    const float* Wq     = (const float*)d_in[3];
    const float* bq     = (const float*)d_in[4];
    const float* Ws     = (const float*)d_in[5];
    const float* v      = (const float*)d_in[6];
    const float* Wc     = (const float*)d_in[7];
    const float* bc     = (const float*)d_in[8];

    float* out_ctx = (float*)d_out;                  // (B,T,2H)
    float* out_hid = out_ctx + BB * TT * H2;         // (B,T,H)
    float* out_att = out_hid + BB * TT * HH;         // (B,S,T)

    static cudaStream_t s1 = nullptr, s2 = nullptr;
    static cudaEvent_t ef, e1, e2;
    if (!s1) {
        cudaStreamCreateWithFlags(&s1, cudaStreamNonBlocking);
        cudaStreamCreateWithFlags(&s2, cudaStreamNonBlocking);
        cudaEventCreateWithFlags(&ef, cudaEventDisableTiming);
        cudaEventCreateWithFlags(&e1, cudaEventDisableTiming);
        cudaEventCreateWithFlags(&e2, cudaEventDisableTiming);
        cudaFuncSetAttribute(align_kernel,
                             cudaFuncAttributeMaxDynamicSharedMemorySize,
                             TT * H2 * sizeof(float));
        cudaFuncSetAttribute(sf_mma,
                             cudaFuncAttributeMaxDynamicSharedMemorySize,
                             SMEM_MMA);
    }

    // fork
    cudaEventRecord(ef, 0);
    cudaStreamWaitEvent(s1, ef, 0);
    cudaStreamWaitEvent(s2, ef, 0);

    prep_B<<<dim3(16, 16), 256, 0, s1>>>(Ws);
    cudaEventRecord(e1, s1);

    zero_kernel<<<32, 256, 0, s2>>>((float4*)out_ctx);
    qf_kernel<<<dim3(8, 4, 4), 128, 0, s2>>>(query, Wq, bq);
    hid_q_kernel<<<dim3(4, 4, 4), 128, 0, s2>>>(query, Wc, bc, out_hid);
    cudaEventRecord(e2, s2);

    prep_A<<<1024, 256>>>(states);
    cudaStreamWaitEvent(0, e1, 0);  // prep_B done
    sf_mma<<<dim3(16, 16), 512, SMEM_MMA>>>();
    cudaStreamWaitEvent(0, e2, 0);  // zero + qf + hid_q done
    align_kernel<<<dim3(32, BB), 512, TT * H2 * sizeof(float)>>>(v);
    softmax_kernel<<<dim3(TT, BB), 256>>>(mask, out_att);
    ctx_kernel<<<dim3(8, 16, 4), 128>>>(states, out_ctx);
    hidden_kernel<<<dim3(4, 4, 32), 128>>>(Wc, out_ctx, out_hid);
}

// round 10
// speedup vs baseline: 3.9538x; 1.0784x over previous
#include <cuda_runtime.h>
#include <cuda_fp16.h>
#include <cstdint>

#define BB 4
#define TT 32
#define SS 1024
#define HH 512
#define H2 1024
#define H3 1536

typedef unsigned long long ull;

// ---------------------------------------------------------------------------
// Scratch (allocation-free: __device__ globals)
// ---------------------------------------------------------------------------
__device__ float g_qf[BB * TT * H2];          // 512 KB
__device__ float g_sf[(size_t)BB * SS * H2];  // 16 MB
__device__ float g_attn[BB * TT * SS];        // 512 KB
// fp16 operands, row-major K-major:
// gA_hi: [4096][1024] fp16 (states, hi only)
// gB_hi/gB_lo: [1024 n][1024 k] fp16 (Ws^T hi/lo split)
__device__ __align__(16) char gA_hi[8 << 20];
__device__ __align__(16) char gB_hi[2 << 20];
__device__ __align__(16) char gB_lo[2 << 20];

__device__ __forceinline__ float tanh_fast(float x) {
    float y;
    asm("tanh.approx.f32 %0, %1;" : "=f"(y) : "f"(x));
    return y;
}

__device__ __forceinline__ uint32_t smem_u32(const void* p) {
    uint32_t a;
    asm("{ .reg .u64 t; cvta.to.shared.u64 t, %1; cvt.u32.u64 %0, t; }" : "=r"(a) : "l"(p));
    return a;
}

__device__ __forceinline__ uint32_t pack2h(float a, float b) {
    __half2 h = __floats2half2_rn(a, b);
    return *(uint32_t*)&h;
}

// ---- baseline-PTX tensor ops (sm_80+) -------------------------------------
#define LDSM_X4(r, a) \
    asm volatile("ldmatrix.sync.aligned.m8n8.x4.shared.b16 {%0,%1,%2,%3}, [%4];" \
                 : "=r"((r)[0]), "=r"((r)[1]), "=r"((r)[2]), "=r"((r)[3]) : "r"(a))

__device__ __forceinline__ void hmma(float* c, const uint32_t* a, uint32_t b0, uint32_t b1) {
    asm volatile(
        "mma.sync.aligned.m16n8k16.row.col.f32.f16.f16.f32 "
        "{%0,%1,%2,%3}, {%4,%5,%6,%7}, {%8,%9}, {%0,%1,%2,%3};"
        : "+f"(c[0]), "+f"(c[1]), "+f"(c[2]), "+f"(c[3])
        : "r"(a[0]), "r"(a[1]), "r"(a[2]), "r"(a[3]), "r"(b0), "r"(b1));
}

#define CP16(s, g) \
    asm volatile("cp.async.cg.shared.global [%0], [%1], 16;" :: "r"(s), "l"(g))
#define CPCOMMIT() asm volatile("cp.async.commit_group;" ::: "memory")
#define CPWAIT1() asm volatile("cp.async.wait_group 1;" ::: "memory")
#define CPWAIT0() asm volatile("cp.async.wait_group 0;" ::: "memory")

// ---------------------------------------------------------------------------
// K0: zero out_ctx + out_hid (atomicAdd targets). 196608 floats = 49152 f4.
// ---------------------------------------------------------------------------
__global__ __launch_bounds__(256) void zero_kernel(float4* __restrict__ p) {
    int i = blockIdx.x * 1024 + threadIdx.x;
#pragma unroll
    for (int u = 0; u < 4; u++) p[i + u * 256] = make_float4(0.f, 0.f, 0.f, 0.f);
}

// ---------------------------------------------------------------------------
// K1: qf = query @ Wq + bq   (128 x 1024, K=512)
// ---------------------------------------------------------------------------
__global__ __launch_bounds__(128) void qf_kernel(const float* __restrict__ query,
                                                 const float* __restrict__ Wq,
                                                 const float* __restrict__ bq) {
    int jc = blockIdx.x, tg = blockIdx.y, b = blockIdx.z;
    int j = jc * 128 + threadIdx.x;
    int t0 = tg * 8;
    __shared__ float q_s[8][HH];
    for (int i = threadIdx.x; i < 8 * HH; i += 128) {
        int r = i >> 9, c = i & (HH - 1);
        q_s[r][c] = query[(size_t)(b * TT + t0 + r) * HH + c];
    }
    __syncthreads();
    float acc[8];
    float bias = bq[j];
#pragma unroll
    for (int i = 0; i < 8; i++) acc[i] = bias;
#pragma unroll 8
    for (int k = 0; k < HH; k++) {
        float w = Wq[(size_t)k * H2 + j];
#pragma unroll
        for (int i = 0; i < 8; i++) acc[i] = fmaf(q_s[i][k], w, acc[i]);
    }
#pragma unroll
    for (int i = 0; i < 8; i++)
        g_qf[(size_t)(b * TT + t0 + i) * H2 + j] = acc[i];
}

// ---------------------------------------------------------------------------
// K1b: out_hid += query @ Wc[1024:1536] (+bc at kc==0). Split-K atomics.
// grid (hc=4, tg=4, b*4+kc=16) = 256 blocks, 128 thr, K-chunk 128.
// ---------------------------------------------------------------------------
__global__ __launch_bounds__(128) void hid_q_kernel(const float* __restrict__ query,
                                                    const float* __restrict__ Wc,
                                                    const float* __restrict__ bc,
                                                    float* __restrict__ out_hid) {
    int hc = blockIdx.x, tg = blockIdx.y;
    int b = blockIdx.z >> 2, kc = blockIdx.z & 3;
    int h = hc * 128 + threadIdx.x;
    int t0 = tg * 8, k0 = kc * 128;
    __shared__ float q_s[8][128];
    for (int i = threadIdx.x; i < 8 * 128; i += 128) {
        int r = i >> 7, c = i & 127;
        q_s[r][c] = query[(size_t)(b * TT + t0 + r) * HH + k0 + c];
    }
    __syncthreads();
    float acc[8];
    float bias = (kc == 0) ? bc[h] : 0.f;
#pragma unroll
    for (int i = 0; i < 8; i++) acc[i] = bias;
#pragma unroll 4
    for (int k = 0; k < 128; k++) {
        float w = Wc[(size_t)(H2 + k0 + k) * HH + h];
#pragma unroll
        for (int i = 0; i < 8; i++) acc[i] = fmaf(q_s[i][k], w, acc[i]);
    }
#pragma unroll
    for (int i = 0; i < 8; i++)
        atomicAdd(&out_hid[(size_t)(b * TT + t0 + i) * HH + h], acc[i]);
}

// ---------------------------------------------------------------------------
// prep_A: states fp32 [4096,1024] -> gA_hi fp16 row-major (hi only).
// ---------------------------------------------------------------------------
__global__ __launch_bounds__(256) void prep_A(const float* __restrict__ A) {
    int idx = blockIdx.x * 256 + threadIdx.x;
#pragma unroll
    for (int q = 0; q < 4; q++) {
        int fid = idx * 4 + q;
        float4 vvv = *(const float4*)(A + (size_t)fid * 4);
        ull hi = (ull)pack2h(vvv.x, vvv.y) | ((ull)pack2h(vvv.z, vvv.w) << 32);
        *(ull*)(gA_hi + (size_t)fid * 8) = hi;
    }
}

// ---------------------------------------------------------------------------
// prep_B: Ws fp32 [K=1024, N=1024] -> gB_hi/gB_lo fp16 transposed [N][K].
// ---------------------------------------------------------------------------
__global__ __launch_bounds__(256) void prep_B(const float* __restrict__ W) {
    __shared__ float tr[64][65];
    int k0 = blockIdx.x * 64, n0 = blockIdx.y * 64;
    int tid = threadIdx.x;
    int ki = tid >> 2, nq = (tid & 3) * 16;
#pragma unroll
    for (int j = 0; j < 4; j++) {
        float4 vv = *(const float4*)(W + (size_t)(k0 + ki) * H2 + n0 + nq + j * 4);
        tr[nq + j * 4 + 0][ki] = vv.x;
        tr[nq + j * 4 + 1][ki] = vv.y;
        tr[nq + j * 4 + 2][ki] = vv.z;
        tr[nq + j * 4 + 3][ki] = vv.w;
    }
    __syncthreads();
    int nr_l = tid >> 2, kq = (tid & 3) * 16;
    int n_g = n0 + nr_l;
#pragma unroll
    for (int j = 0; j < 4; j++) {
        int kr = kq + j * 4;
        float x0 = tr[nr_l][kr], x1 = tr[nr_l][kr + 1];
        float x2 = tr[nr_l][kr + 2], x3 = tr[nr_l][kr + 3];
        float h0 = __half2float(__float2half_rn(x0));
        float h1 = __half2float(__float2half_rn(x1));
        float h2 = __half2float(__float2half_rn(x2));
        float h3 = __half2float(__float2half_rn(x3));
        ull hi = (ull)pack2h(h0, h1) | ((ull)pack2h(h2, h3) << 32);
        ull lo = (ull)pack2h(x0 - h0, x1 - h1) |
                 ((ull)pack2h(x2 - h2, x3 - h3) << 32);
        size_t off = ((size_t)n_g * H2 + k0 + kr) * 2;
        *(ull*)(gB_hi + off) = hi;
        *(ull*)(gB_lo + off) = lo;
    }
}

// ---------------------------------------------------------------------------
// K2: sf = states @ Ws via mma.sync fp16 2-MMA split (Ah*Bh + Ah*Bl).
// Block tile 256(M) x 64(N), 512 threads, warp tile 64x16, grid 16x16 = 256
// blocks = 2 waves, K-chunks 64, cp.async double buffer, 144B rows.
// ---------------------------------------------------------------------------
#define ROWB 144
#define A_TILE (256 * ROWB)           // 36864
#define B_TILE (64 * ROWB)            // 9216
#define STAGEB (A_TILE + 2 * B_TILE)  // 55296
#define SMEM_MMA (2 * STAGEB)         // 110592

__device__ __forceinline__ void load_chunk(uint32_t sst, const char* gAh,
                                           const char* gBh, const char* gBl,
                                           int c, int tid) {
#pragma unroll
    for (int r = 0; r < 4; r++) {
        int i = r * 512 + tid;
        int row = i >> 3, quad = i & 7;
        uint32_t soff = row * ROWB + quad * 16;
        size_t goff = (size_t)row * 2048 + (size_t)c * 128 + quad * 16;
        CP16(sst + soff, gAh + goff);
    }
    {
        int row = tid >> 3, quad = tid & 7;
        uint32_t soff = row * ROWB + quad * 16;
        size_t goff = (size_t)row * 2048 + (size_t)c * 128 + quad * 16;
        CP16(sst + A_TILE + soff, gBh + goff);
        CP16(sst + A_TILE + B_TILE + soff, gBl + goff);
    }
}

__global__ __launch_bounds__(512, 1) void sf_mma() {
    extern __shared__ __align__(16) char sm[];
    uint32_t sbase = smem_u32(sm);
    int tid = threadIdx.x, lane = tid & 31, warp = tid >> 5;
    int nt = blockIdx.x, mt = blockIdx.y;
    int wm = warp >> 2, wn = warp & 3;

    const char* gAh = gA_hi + (size_t)(mt * 256) * 2048;
    const char* gBh = gB_hi + (size_t)(nt * 64) * 2048;
    const char* gBl = gB_lo + (size_t)(nt * 64) * 2048;

    float cacc[4][2][4] = {};

    load_chunk(sbase, gAh, gBh, gBl, 0, tid);
    CPCOMMIT();

#pragma unroll 1
    for (int c = 0; c < 16; c++) {
        int cur = c & 1;
        if (c + 1 < 16) {
            load_chunk(sbase + (cur ^ 1) * STAGEB, gAh, gBh, gBl, c + 1, tid);
            CPCOMMIT();
            CPWAIT1();
        } else {
            CPWAIT0();
        }
        __syncthreads();

        uint32_t sA = sbase + cur * STAGEB;
        uint32_t sB_h = sA + A_TILE;
        uint32_t sB_l = sB_h + B_TILE;
        int r16 = lane & 15, hx = lane >> 4;

#pragma unroll
        for (int k16 = 0; k16 < 4; k16++) {
            int kb = k16 * 32 + hx * 16;
            uint32_t ah[4][4];
#pragma unroll
            for (int mf = 0; mf < 4; mf++)
                LDSM_X4(ah[mf], sA + (wm * 64 + mf * 16 + r16) * ROWB + kb);
            {
                uint32_t bh[4];
                LDSM_X4(bh, sB_h + (wn * 16 + r16) * ROWB + kb);
#pragma unroll
                for (int mf = 0; mf < 4; mf++)
#pragma unroll
                    for (int nf = 0; nf < 2; nf++)
                        hmma(cacc[mf][nf], ah[mf], bh[nf], bh[nf + 2]);
            }
            {
                uint32_t bl[4];
                LDSM_X4(bl, sB_l + (wn * 16 + r16) * ROWB + kb);
#pragma unroll
                for (int mf = 0; mf < 4; mf++)
#pragma unroll
                    for (int nf = 0; nf < 2; nf++)
                        hmma(cacc[mf][nf], ah[mf], bl[nf], bl[nf + 2]);
            }
        }
        __syncthreads();
    }

    int tg = lane >> 2, tq = lane & 3;
#pragma unroll
    for (int mf = 0; mf < 4; mf++) {
#pragma unroll
        for (int nf = 0; nf < 2; nf++) {
            float* base = g_sf + (size_t)(mt * 256 + wm * 64 + mf * 16 + tg) * H2 +
                          nt * 64 + wn * 16 + nf * 8 + tq * 2;
            float2 v0 = {cacc[mf][nf][0], cacc[mf][nf][1]};
            float2 v1 = {cacc[mf][nf][2], cacc[mf][nf][3]};
            *(float2*)base = v0;
            *(float2*)(base + 8 * H2) = v1;
        }
    }
}

// ---------------------------------------------------------------------------
// K3a: raw alignments. Block (sc, b), 512 thr, qf[b] in smem; 2 s-rows/warp
// preloaded in regs so each q LDS.128 feeds 8 tanh-FMAs.
// ---------------------------------------------------------------------------
__global__ __launch_bounds__(512, 1) void align_kernel(const float* __restrict__ v) {
    extern __shared__ float qf_s[];  // [TT][H2] = 128 KB
    int sc = blockIdx.x, b = blockIdx.y;
    int tid = threadIdx.x, lane = tid & 31, warp = tid >> 5;

    const float4* qsrc = (const float4*)(g_qf + (size_t)b * TT * H2);
    float4* qdst = (float4*)qf_s;
#pragma unroll
    for (int i = 0; i < 16; i++) qdst[tid + i * 512] = qsrc[tid + i * 512];

    int s0 = sc * 32 + warp * 2;
    float4 sv[2][8];
#pragma unroll
    for (int si = 0; si < 2; si++) {
        const float* sfrow = g_sf + ((size_t)(b * SS + s0 + si)) * H2;
#pragma unroll
        for (int u = 0; u < 8; u++)
            sv[si][u] = *(const float4*)(sfrow + u * 128 + lane * 4);
    }
    __syncthreads();

    float* ga = g_attn + (size_t)(b * TT) * SS + s0;
#pragma unroll 1
    for (int t = 0; t < TT; t++) {
        const float* qrow = qf_s + t * H2;
        float a00 = 0.f, a01 = 0.f, a10 = 0.f, a11 = 0.f;
#pragma unroll
        for (int u = 0; u < 8; u++) {
            float4 q = *(const float4*)(qrow + u * 128 + lane * 4);
            float4 vv = __ldg((const float4*)(v + u * 128 + lane * 4));
            a00 = fmaf(tanh_fast(q.x + sv[0][u].x), vv.x, a00);
            a01 = fmaf(tanh_fast(q.y + sv[0][u].y), vv.y, a01);
            a00 = fmaf(tanh_fast(q.z + sv[0][u].z), vv.z, a00);
            a01 = fmaf(tanh_fast(q.w + sv[0][u].w), vv.w, a01);
            a10 = fmaf(tanh_fast(q.x + sv[1][u].x), vv.x, a10);
            a11 = fmaf(tanh_fast(q.y + sv[1][u].y), vv.y, a11);
            a10 = fmaf(tanh_fast(q.z + sv[1][u].z), vv.z, a10);
            a11 = fmaf(tanh_fast(q.w + sv[1][u].w), vv.w, a11);
        }
        float acc0 = a00 + a01;
        float acc1 = a10 + a11;
#pragma unroll
        for (int o = 16; o; o >>= 1) {
            acc0 += __shfl_xor_sync(0xffffffffu, acc0, o);
            acc1 += __shfl_xor_sync(0xffffffffu, acc1, o);
        }
        if (lane == 0) {
            ga[(size_t)t * SS] = acc0;
            ga[(size_t)t * SS + 1] = acc1;
        }
    }
}

// ---------------------------------------------------------------------------
// K3b: mask + softmax.
// ---------------------------------------------------------------------------
__global__ __launch_bounds__(256) void softmax_kernel(const int* __restrict__ mask,
                                                      float* __restrict__ out_att) {
    int t = blockIdx.x, b = blockIdx.y;
    int tid = threadIdx.x, lane = tid & 31, warp = tid >> 5;
    __shared__ float red[8];

    float* ga = g_attn + (size_t)(b * TT + t) * SS;
    float al[4];
#pragma unroll
    for (int i = 0; i < 4; i++) {
        int s = tid + i * 256;
        al[i] = mask[b * SS + s] ? ga[s] : -1e30f;
    }

    float m = fmaxf(fmaxf(al[0], al[1]), fmaxf(al[2], al[3]));
#pragma unroll
    for (int o = 16; o; o >>= 1) m = fmaxf(m, __shfl_xor_sync(0xffffffffu, m, o));
    if (lane == 0) red[warp] = m;
    __syncthreads();
    float mx = -1e30f;
#pragma unroll
    for (int i = 0; i < 8; i++) mx = fmaxf(mx, red[i]);

    float e[4];
    float ssum = 0.f;
#pragma unroll
    for (int i = 0; i < 4; i++) {
        e[i] = __expf(al[i] - mx);
        ssum += e[i];
    }
#pragma unroll
    for (int o = 16; o; o >>= 1) ssum += __shfl_xor_sync(0xffffffffu, ssum, o);
    __syncthreads();
    if (lane == 0) red[warp] = ssum;
    __syncthreads();
    float tot = 0.f;
#pragma unroll
    for (int i = 0; i < 8; i++) tot += red[i];
    float inv = 1.0f / tot;

    float* oa = out_att + (size_t)b * SS * TT + t;
#pragma unroll
    for (int i = 0; i < 4; i++) {
        int s = tid + i * 256;
        float w = e[i] * inv;
        ga[s] = w;
        oa[(size_t)s * TT] = w;
    }
}

// ---------------------------------------------------------------------------
// K4: context = attn @ states, split-S (64) with atomicAdd epilogue.
// ---------------------------------------------------------------------------
__global__ __launch_bounds__(128) void ctx_kernel(const float* __restrict__ states,
                                                  float* __restrict__ out_ctx) {
    int dc = blockIdx.x, sc = blockIdx.y, b = blockIdx.z;
    int d = dc * 128 + threadIdx.x;
    int s0 = sc * 64;
    __shared__ float aw[TT][64];
    for (int i = threadIdx.x; i < TT * 64; i += 128) {
        int t = i >> 6, sl = i & 63;
        aw[t][sl] = g_attn[(size_t)(b * TT + t) * SS + s0 + sl];
    }
    __syncthreads();
    float acc[TT] = {};
    const float* sb = states + ((size_t)b * SS + s0) * H2 + d;
#pragma unroll 4
    for (int sl = 0; sl < 64; sl++) {
        float sv = sb[(size_t)sl * H2];
#pragma unroll
        for (int t = 0; t < TT; t++) acc[t] = fmaf(aw[t][sl], sv, acc[t]);
    }
#pragma unroll
    for (int t = 0; t < TT; t++)
        atomicAdd(&out_ctx[(size_t)(b * TT + t) * H2 + d], acc[t]);
}

// ---------------------------------------------------------------------------
// K5: attention_hidden += context @ Wc[0:1024]. Split-K atomics.
// ---------------------------------------------------------------------------
__global__ __launch_bounds__(128) void hidden_kernel(const float* __restrict__ Wc,
                                                     const float* __restrict__ ctx,
                                                     float* __restrict__ out_hid) {
    int hc = blockIdx.x, tg = blockIdx.y;
    int b = blockIdx.z >> 3, kc = blockIdx.z & 7;
    int h = hc * 128 + threadIdx.x;
    int t0 = tg * 8, k0 = kc * 128;
    __shared__ float cc[8][128];
    for (int i = threadIdx.x; i < 8 * 128; i += 128) {
        int r = i >> 7, col = i & 127;
        cc[r][col] = ctx[(size_t)(b * TT + t0 + r) * H2 + k0 + col];
    }
    __syncthreads();
    float acc[8] = {};
#pragma unroll 4
    for (int k = 0; k < 128; k++) {
        float w = Wc[(size_t)(k0 + k) * HH + h];
#pragma unroll
        for (int i = 0; i < 8; i++) acc[i] = fmaf(cc[i][k], w, acc[i]);
    }
#pragma unroll
    for (int i = 0; i < 8; i++)
        atomicAdd(&out_hid[(size_t)(b * TT + t0 + i) * HH + h], acc[i]);
}

// ---------------------------------------------------------------------------
extern "C" void kernel_launch(void* const* d_in, const int* in_sizes, int n_in,
                              void* d_out, int out_size) {
    const float* query  = (const float*)d_in[0];
    const float* states = (const float*)d_in[1];
    const int*   mask   = (const int*)d_in[2];
    const float* Wq     = (const float*)d_in[3];
    const float* bq     = (const float*)d_in[4];
    const float* Ws     = (const float*)d_in[5];
    const float* v      = (const float*)d_in[6];
    const float* Wc     = (const float*)d_in[7];
    const float* bc     = (const float*)d_in[8];

    float* out_ctx = (float*)d_out;                  // (B,T,2H)
    float* out_hid = out_ctx + BB * TT * H2;         // (B,T,H)
    float* out_att = out_hid + BB * TT * HH;         // (B,S,T)

    static cudaStream_t s1 = nullptr, s2 = nullptr;
    static cudaEvent_t ef, e1, e2;
    if (!s1) {
        cudaStreamCreateWithFlags(&s1, cudaStreamNonBlocking);
        cudaStreamCreateWithFlags(&s2, cudaStreamNonBlocking);
        cudaEventCreateWithFlags(&ef, cudaEventDisableTiming);
        cudaEventCreateWithFlags(&e1, cudaEventDisableTiming);
        cudaEventCreateWithFlags(&e2, cudaEventDisableTiming);
        cudaFuncSetAttribute(align_kernel,
                             cudaFuncAttributeMaxDynamicSharedMemorySize,
                             TT * H2 * sizeof(float));
        cudaFuncSetAttribute(sf_mma,
                             cudaFuncAttributeMaxDynamicSharedMemorySize,
                             SMEM_MMA);
    }

    // fork
    cudaEventRecord(ef, 0);
    cudaStreamWaitEvent(s1, ef, 0);
    cudaStreamWaitEvent(s2, ef, 0);

    prep_B<<<dim3(16, 16), 256, 0, s1>>>(Ws);
    cudaEventRecord(e1, s1);

    zero_kernel<<<48, 256, 0, s2>>>((float4*)out_ctx);  // ctx + hid
    qf_kernel<<<dim3(8, 4, 4), 128, 0, s2>>>(query, Wq, bq);
    hid_q_kernel<<<dim3(4, 4, 16), 128, 0, s2>>>(query, Wc, bc, out_hid);
    cudaEventRecord(e2, s2);

    prep_A<<<1024, 256>>>(states);
    cudaStreamWaitEvent(0, e1, 0);  // prep_B done
    sf_mma<<<dim3(16, 16), 512, SMEM_MMA>>>();
    cudaStreamWaitEvent(0, e2, 0);  // zero + qf + hid_q done
    align_kernel<<<dim3(32, BB), 512, TT * H2 * sizeof(float)>>>(v);
    softmax_kernel<<<dim3(TT, BB), 256>>>(mask, out_att);
    ctx_kernel<<<dim3(8, 16, 4), 128>>>(states, out_ctx);
    hidden_kernel<<<dim3(4, 4, 32), 128>>>(Wc, out_ctx, out_hid);
}

// round 11
// speedup vs baseline: 4.1750x; 1.0559x over previous
#include <cuda_runtime.h>
#include <cuda_fp16.h>
#include <cstdint>

#define BB 4
#define TT 32
#define SS 1024
#define HH 512
#define H2 1024
#define H3 1536

typedef unsigned long long ull;

// ---------------------------------------------------------------------------
// Scratch (allocation-free: __device__ globals)
// ---------------------------------------------------------------------------
__device__ float g_qf[BB * TT * H2];          // 512 KB
__device__ float g_sf[(size_t)BB * SS * H2];  // 16 MB
__device__ float g_attn[BB * TT * SS];        // 512 KB
// fp16 operands, row-major K-major:
// gA_hi: [4096][1024] fp16 (states, hi only)
// gB_hi/gB_lo: [1024 n][1024 k] fp16 (Ws^T hi/lo split)
__device__ __align__(16) char gA_hi[8 << 20];
__device__ __align__(16) char gB_hi[2 << 20];
__device__ __align__(16) char gB_lo[2 << 20];

__device__ __forceinline__ uint32_t smem_u32(const void* p) {
    uint32_t a;
    asm("{ .reg .u64 t; cvta.to.shared.u64 t, %1; cvt.u32.u64 %0, t; }" : "=r"(a) : "l"(p));
    return a;
}

__device__ __forceinline__ uint32_t pack2h(float a, float b) {
    __half2 h = __floats2half2_rn(a, b);
    return *(uint32_t*)&h;
}

// f16x2 tanh path: pack two f32 -> f16x2, MUFU tanh on both halves, unpack.
__device__ __forceinline__ uint32_t f16x2_pack(float lo, float hi) {
    uint32_t r;
    asm("cvt.rn.f16x2.f32 %0, %1, %2;" : "=r"(r) : "f"(hi), "f"(lo));
    return r;
}
__device__ __forceinline__ uint32_t tanh_h2(uint32_t x) {
    uint32_t y;
    asm("tanh.approx.f16x2 %0, %1;" : "=r"(y) : "r"(x));
    return y;
}
__device__ __forceinline__ float2 f16x2_unpack(uint32_t p) {
    float lo, hi;
    asm("{ .reg .b16 l, h; mov.b32 {l, h}, %2; cvt.f32.f16 %0, l; cvt.f32.f16 %1, h; }"
        : "=f"(lo), "=f"(hi) : "r"(p));
    return make_float2(lo, hi);
}

// ---- baseline-PTX tensor ops (sm_80+) -------------------------------------
#define LDSM_X4(r, a) \
    asm volatile("ldmatrix.sync.aligned.m8n8.x4.shared.b16 {%0,%1,%2,%3}, [%4];" \
                 : "=r"((r)[0]), "=r"((r)[1]), "=r"((r)[2]), "=r"((r)[3]) : "r"(a))

__device__ __forceinline__ void hmma(float* c, const uint32_t* a, uint32_t b0, uint32_t b1) {
    asm volatile(
        "mma.sync.aligned.m16n8k16.row.col.f32.f16.f16.f32 "
        "{%0,%1,%2,%3}, {%4,%5,%6,%7}, {%8,%9}, {%0,%1,%2,%3};"
        : "+f"(c[0]), "+f"(c[1]), "+f"(c[2]), "+f"(c[3])
        : "r"(a[0]), "r"(a[1]), "r"(a[2]), "r"(a[3]), "r"(b0), "r"(b1));
}

#define CP16(s, g) \
    asm volatile("cp.async.cg.shared.global [%0], [%1], 16;" :: "r"(s), "l"(g))
#define CPCOMMIT() asm volatile("cp.async.commit_group;" ::: "memory")
#define CPWAIT1() asm volatile("cp.async.wait_group 1;" ::: "memory")
#define CPWAIT0() asm volatile("cp.async.wait_group 0;" ::: "memory")

// ---------------------------------------------------------------------------
// K0: zero out_ctx + out_hid (atomicAdd targets). 196608 floats = 49152 f4.
// ---------------------------------------------------------------------------
__global__ __launch_bounds__(256) void zero_kernel(float4* __restrict__ p) {
    int i = blockIdx.x * 1024 + threadIdx.x;
#pragma unroll
    for (int u = 0; u < 4; u++) p[i + u * 256] = make_float4(0.f, 0.f, 0.f, 0.f);
}

// ---------------------------------------------------------------------------
// K1: qf = query @ Wq + bq   (128 x 1024, K=512)
// ---------------------------------------------------------------------------
__global__ __launch_bounds__(128) void qf_kernel(const float* __restrict__ query,
                                                 const float* __restrict__ Wq,
                                                 const float* __restrict__ bq) {
    int jc = blockIdx.x, tg = blockIdx.y, b = blockIdx.z;
    int j = jc * 128 + threadIdx.x;
    int t0 = tg * 8;
    __shared__ float q_s[8][HH];
    for (int i = threadIdx.x; i < 8 * HH; i += 128) {
        int r = i >> 9, c = i & (HH - 1);
        q_s[r][c] = query[(size_t)(b * TT + t0 + r) * HH + c];
    }
    __syncthreads();
    float acc[8];
    float bias = bq[j];
#pragma unroll
    for (int i = 0; i < 8; i++) acc[i] = bias;
#pragma unroll 8
    for (int k = 0; k < HH; k++) {
        float w = Wq[(size_t)k * H2 + j];
#pragma unroll
        for (int i = 0; i < 8; i++) acc[i] = fmaf(q_s[i][k], w, acc[i]);
    }
#pragma unroll
    for (int i = 0; i < 8; i++)
        g_qf[(size_t)(b * TT + t0 + i) * H2 + j] = acc[i];
}

// ---------------------------------------------------------------------------
// K1b: out_hid += query @ Wc[1024:1536] (+bc at kc==0). Split-K atomics.
// grid (hc=4, tg=4, b*8+kc=32) = 512 blocks, 128 thr, K-chunk 64.
// ---------------------------------------------------------------------------
__global__ __launch_bounds__(128) void hid_q_kernel(const float* __restrict__ query,
                                                    const float* __restrict__ Wc,
                                                    const float* __restrict__ bc,
                                                    float* __restrict__ out_hid) {
    int hc = blockIdx.x, tg = blockIdx.y;
    int b = blockIdx.z >> 3, kc = blockIdx.z & 7;
    int h = hc * 128 + threadIdx.x;
    int t0 = tg * 8, k0 = kc * 64;
    __shared__ float q_s[8][64];
    for (int i = threadIdx.x; i < 8 * 64; i += 128) {
        int r = i >> 6, c = i & 63;
        q_s[r][c] = query[(size_t)(b * TT + t0 + r) * HH + k0 + c];
    }
    __syncthreads();
    float acc[8];
    float bias = (kc == 0) ? bc[h] : 0.f;
#pragma unroll
    for (int i = 0; i < 8; i++) acc[i] = bias;
#pragma unroll 4
    for (int k = 0; k < 64; k++) {
        float w = Wc[(size_t)(H2 + k0 + k) * HH + h];
#pragma unroll
        for (int i = 0; i < 8; i++) acc[i] = fmaf(q_s[i][k], w, acc[i]);
    }
#pragma unroll
    for (int i = 0; i < 8; i++)
        atomicAdd(&out_hid[(size_t)(b * TT + t0 + i) * HH + h], acc[i]);
}

// ---------------------------------------------------------------------------
// prep_A: states fp32 [4096,1024] -> gA_hi fp16 row-major (hi only).
// ---------------------------------------------------------------------------
__global__ __launch_bounds__(256) void prep_A(const float* __restrict__ A) {
    int idx = blockIdx.x * 256 + threadIdx.x;
#pragma unroll
    for (int q = 0; q < 4; q++) {
        int fid = idx * 4 + q;
        float4 vvv = *(const float4*)(A + (size_t)fid * 4);
        ull hi = (ull)pack2h(vvv.x, vvv.y) | ((ull)pack2h(vvv.z, vvv.w) << 32);
        *(ull*)(gA_hi + (size_t)fid * 8) = hi;
    }
}

// ---------------------------------------------------------------------------
// prep_B: Ws fp32 [K=1024, N=1024] -> gB_hi/gB_lo fp16 transposed [N][K].
// ---------------------------------------------------------------------------
__global__ __launch_bounds__(256) void prep_B(const float* __restrict__ W) {
    __shared__ float tr[64][65];
    int k0 = blockIdx.x * 64, n0 = blockIdx.y * 64;
    int tid = threadIdx.x;
    int ki = tid >> 2, nq = (tid & 3) * 16;
#pragma unroll
    for (int j = 0; j < 4; j++) {
        float4 vv = *(const float4*)(W + (size_t)(k0 + ki) * H2 + n0 + nq + j * 4);
        tr[nq + j * 4 + 0][ki] = vv.x;
        tr[nq + j * 4 + 1][ki] = vv.y;
        tr[nq + j * 4 + 2][ki] = vv.z;
        tr[nq + j * 4 + 3][ki] = vv.w;
    }
    __syncthreads();
    int nr_l = tid >> 2, kq = (tid & 3) * 16;
    int n_g = n0 + nr_l;
#pragma unroll
    for (int j = 0; j < 4; j++) {
        int kr = kq + j * 4;
        float x0 = tr[nr_l][kr], x1 = tr[nr_l][kr + 1];
        float x2 = tr[nr_l][kr + 2], x3 = tr[nr_l][kr + 3];
        float h0 = __half2float(__float2half_rn(x0));
        float h1 = __half2float(__float2half_rn(x1));
        float h2 = __half2float(__float2half_rn(x2));
        float h3 = __half2float(__float2half_rn(x3));
        ull hi = (ull)pack2h(h0, h1) | ((ull)pack2h(h2, h3) << 32);
        ull lo = (ull)pack2h(x0 - h0, x1 - h1) |
                 ((ull)pack2h(x2 - h2, x3 - h3) << 32);
        size_t off = ((size_t)n_g * H2 + k0 + kr) * 2;
        *(ull*)(gB_hi + off) = hi;
        *(ull*)(gB_lo + off) = lo;
    }
}

// ---------------------------------------------------------------------------
// K2: sf = states @ Ws via mma.sync fp16 2-MMA split (Ah*Bh + Ah*Bl).
// Block tile 256(M) x 64(N), 512 threads, warp tile 64x16, grid 16x16 = 256
// blocks = 2 waves, K-chunks 64, cp.async double buffer, 144B rows.
// ---------------------------------------------------------------------------
#define ROWB 144
#define A_TILE (256 * ROWB)           // 36864
#define B_TILE (64 * ROWB)            // 9216
#define STAGEB (A_TILE + 2 * B_TILE)  // 55296
#define SMEM_MMA (2 * STAGEB)         // 110592

__device__ __forceinline__ void load_chunk(uint32_t sst, const char* gAh,
                                           const char* gBh, const char* gBl,
                                           int c, int tid) {
#pragma unroll
    for (int r = 0; r < 4; r++) {
        int i = r * 512 + tid;
        int row = i >> 3, quad = i & 7;
        uint32_t soff = row * ROWB + quad * 16;
        size_t goff = (size_t)row * 2048 + (size_t)c * 128 + quad * 16;
        CP16(sst + soff, gAh + goff);
    }
    {
        int row = tid >> 3, quad = tid & 7;
        uint32_t soff = row * ROWB + quad * 16;
        size_t goff = (size_t)row * 2048 + (size_t)c * 128 + quad * 16;
        CP16(sst + A_TILE + soff, gBh + goff);
        CP16(sst + A_TILE + B_TILE + soff, gBl + goff);
    }
}

__global__ __launch_bounds__(512, 1) void sf_mma() {
    extern __shared__ __align__(16) char sm[];
    uint32_t sbase = smem_u32(sm);
    int tid = threadIdx.x, lane = tid & 31, warp = tid >> 5;
    int nt = blockIdx.x, mt = blockIdx.y;
    int wm = warp >> 2, wn = warp & 3;

    const char* gAh = gA_hi + (size_t)(mt * 256) * 2048;
    const char* gBh = gB_hi + (size_t)(nt * 64) * 2048;
    const char* gBl = gB_lo + (size_t)(nt * 64) * 2048;

    float cacc[4][2][4] = {};

    load_chunk(sbase, gAh, gBh, gBl, 0, tid);
    CPCOMMIT();

#pragma unroll 1
    for (int c = 0; c < 16; c++) {
        int cur = c & 1;
        if (c + 1 < 16) {
            load_chunk(sbase + (cur ^ 1) * STAGEB, gAh, gBh, gBl, c + 1, tid);
            CPCOMMIT();
            CPWAIT1();
        } else {
            CPWAIT0();
        }
        __syncthreads();

        uint32_t sA = sbase + cur * STAGEB;
        uint32_t sB_h = sA + A_TILE;
        uint32_t sB_l = sB_h + B_TILE;
        int r16 = lane & 15, hx = lane >> 4;

#pragma unroll
        for (int k16 = 0; k16 < 4; k16++) {
            int kb = k16 * 32 + hx * 16;
            uint32_t ah[4][4];
#pragma unroll
            for (int mf = 0; mf < 4; mf++)
                LDSM_X4(ah[mf], sA + (wm * 64 + mf * 16 + r16) * ROWB + kb);
            {
                uint32_t bh[4];
                LDSM_X4(bh, sB_h + (wn * 16 + r16) * ROWB + kb);
#pragma unroll
                for (int mf = 0; mf < 4; mf++)
#pragma unroll
                    for (int nf = 0; nf < 2; nf++)
                        hmma(cacc[mf][nf], ah[mf], bh[nf], bh[nf + 2]);
            }
            {
                uint32_t bl[4];
                LDSM_X4(bl, sB_l + (wn * 16 + r16) * ROWB + kb);
#pragma unroll
                for (int mf = 0; mf < 4; mf++)
#pragma unroll
                    for (int nf = 0; nf < 2; nf++)
                        hmma(cacc[mf][nf], ah[mf], bl[nf], bl[nf + 2]);
            }
        }
        __syncthreads();
    }

    int tg = lane >> 2, tq = lane & 3;
#pragma unroll
    for (int mf = 0; mf < 4; mf++) {
#pragma unroll
        for (int nf = 0; nf < 2; nf++) {
            float* base = g_sf + (size_t)(mt * 256 + wm * 64 + mf * 16 + tg) * H2 +
                          nt * 64 + wn * 16 + nf * 8 + tq * 2;
            float2 v0 = {cacc[mf][nf][0], cacc[mf][nf][1]};
            float2 v1 = {cacc[mf][nf][2], cacc[mf][nf][3]};
            *(float2*)base = v0;
            *(float2*)(base + 8 * H2) = v1;
        }
    }
}

// ---------------------------------------------------------------------------
// K3a: raw alignments, f16x2 tanh (half the MUFU issue). Block (sc, b),
// 512 thr, qf[b] in smem; 2 s-rows/warp preloaded in regs.
// ---------------------------------------------------------------------------
__global__ __launch_bounds__(512, 1) void align_kernel(const float* __restrict__ v) {
    extern __shared__ float qf_s[];  // [TT][H2] = 128 KB
    int sc = blockIdx.x, b = blockIdx.y;
    int tid = threadIdx.x, lane = tid & 31, warp = tid >> 5;

    const float4* qsrc = (const float4*)(g_qf + (size_t)b * TT * H2);
    float4* qdst = (float4*)qf_s;
#pragma unroll
    for (int i = 0; i < 16; i++) qdst[tid + i * 512] = qsrc[tid + i * 512];

    int s0 = sc * 32 + warp * 2;
    float4 sv[2][8];
#pragma unroll
    for (int si = 0; si < 2; si++) {
        const float* sfrow = g_sf + ((size_t)(b * SS + s0 + si)) * H2;
#pragma unroll
        for (int u = 0; u < 8; u++)
            sv[si][u] = *(const float4*)(sfrow + u * 128 + lane * 4);
    }
    __syncthreads();

    float* ga = g_attn + (size_t)(b * TT) * SS + s0;
#pragma unroll 1
    for (int t = 0; t < TT; t++) {
        const float* qrow = qf_s + t * H2;
        float a00 = 0.f, a01 = 0.f, a10 = 0.f, a11 = 0.f;
#pragma unroll
        for (int u = 0; u < 8; u++) {
            float4 q = *(const float4*)(qrow + u * 128 + lane * 4);
            float4 vv = __ldg((const float4*)(v + u * 128 + lane * 4));
            uint32_t p0 = tanh_h2(f16x2_pack(q.x + sv[0][u].x, q.y + sv[0][u].y));
            uint32_t p1 = tanh_h2(f16x2_pack(q.z + sv[0][u].z, q.w + sv[0][u].w));
            uint32_t p2 = tanh_h2(f16x2_pack(q.x + sv[1][u].x, q.y + sv[1][u].y));
            uint32_t p3 = tanh_h2(f16x2_pack(q.z + sv[1][u].z, q.w + sv[1][u].w));
            float2 t0 = f16x2_unpack(p0), t1 = f16x2_unpack(p1);
            float2 t2 = f16x2_unpack(p2), t3 = f16x2_unpack(p3);
            a00 = fmaf(t0.x, vv.x, a00);
            a01 = fmaf(t0.y, vv.y, a01);
            a00 = fmaf(t1.x, vv.z, a00);
            a01 = fmaf(t1.y, vv.w, a01);
            a10 = fmaf(t2.x, vv.x, a10);
            a11 = fmaf(t2.y, vv.y, a11);
            a10 = fmaf(t3.x, vv.z, a10);
            a11 = fmaf(t3.y, vv.w, a11);
        }
        float acc0 = a00 + a01;
        float acc1 = a10 + a11;
#pragma unroll
        for (int o = 16; o; o >>= 1) {
            acc0 += __shfl_xor_sync(0xffffffffu, acc0, o);
            acc1 += __shfl_xor_sync(0xffffffffu, acc1, o);
        }
        if (lane == 0) {
            ga[(size_t)t * SS] = acc0;
            ga[(size_t)t * SS + 1] = acc1;
        }
    }
}

// ---------------------------------------------------------------------------
// K3b: mask + softmax.
// ---------------------------------------------------------------------------
__global__ __launch_bounds__(256) void softmax_kernel(const int* __restrict__ mask,
                                                      float* __restrict__ out_att) {
    int t = blockIdx.x, b = blockIdx.y;
    int tid = threadIdx.x, lane = tid & 31, warp = tid >> 5;
    __shared__ float red[8];

    float* ga = g_attn + (size_t)(b * TT + t) * SS;
    float al[4];
#pragma unroll
    for (int i = 0; i < 4; i++) {
        int s = tid + i * 256;
        al[i] = mask[b * SS + s] ? ga[s] : -1e30f;
    }

    float m = fmaxf(fmaxf(al[0], al[1]), fmaxf(al[2], al[3]));
#pragma unroll
    for (int o = 16; o; o >>= 1) m = fmaxf(m, __shfl_xor_sync(0xffffffffu, m, o));
    if (lane == 0) red[warp] = m;
    __syncthreads();
    float mx = -1e30f;
#pragma unroll
    for (int i = 0; i < 8; i++) mx = fmaxf(mx, red[i]);

    float e[4];
    float ssum = 0.f;
#pragma unroll
    for (int i = 0; i < 4; i++) {
        e[i] = __expf(al[i] - mx);
        ssum += e[i];
    }
#pragma unroll
    for (int o = 16; o; o >>= 1) ssum += __shfl_xor_sync(0xffffffffu, ssum, o);
    __syncthreads();
    if (lane == 0) red[warp] = ssum;
    __syncthreads();
    float tot = 0.f;
#pragma unroll
    for (int i = 0; i < 8; i++) tot += red[i];
    float inv = 1.0f / tot;

    float* oa = out_att + (size_t)b * SS * TT + t;
#pragma unroll
    for (int i = 0; i < 4; i++) {
        int s = tid + i * 256;
        float w = e[i] * inv;
        ga[s] = w;
        oa[(size_t)s * TT] = w;
    }
}

// ---------------------------------------------------------------------------
// K4: context = attn @ states, split-S (32) with atomicAdd epilogue.
// grid (dc=8, sc=32, b=4) = 1024 blocks, 128 thr.
// ---------------------------------------------------------------------------
__global__ __launch_bounds__(128) void ctx_kernel(const float* __restrict__ states,
                                                  float* __restrict__ out_ctx) {
    int dc = blockIdx.x, sc = blockIdx.y, b = blockIdx.z;
    int d = dc * 128 + threadIdx.x;
    int s0 = sc * 32;
    __shared__ float aw[TT][32];
    for (int i = threadIdx.x; i < TT * 32; i += 128) {
        int t = i >> 5, sl = i & 31;
        aw[t][sl] = g_attn[(size_t)(b * TT + t) * SS + s0 + sl];
    }
    __syncthreads();
    float acc[TT] = {};
    const float* sb = states + ((size_t)b * SS + s0) * H2 + d;
#pragma unroll 4
    for (int sl = 0; sl < 32; sl++) {
        float sv = sb[(size_t)sl * H2];
#pragma unroll
        for (int t = 0; t < TT; t++) acc[t] = fmaf(aw[t][sl], sv, acc[t]);
    }
#pragma unroll
    for (int t = 0; t < TT; t++)
        atomicAdd(&out_ctx[(size_t)(b * TT + t) * H2 + d], acc[t]);
}

// ---------------------------------------------------------------------------
// K5: attention_hidden += context @ Wc[0:1024]. Split-K atomics.
// grid (hc=4, tg=4, b*16+kc=64) = 1024 blocks, 128 thr, K-chunk 64.
// ---------------------------------------------------------------------------
__global__ __launch_bounds__(128) void hidden_kernel(const float* __restrict__ Wc,
                                                     const float* __restrict__ ctx,
                                                     float* __restrict__ out_hid) {
    int hc = blockIdx.x, tg = blockIdx.y;
    int b = blockIdx.z >> 4, kc = blockIdx.z & 15;
    int h = hc * 128 + threadIdx.x;
    int t0 = tg * 8, k0 = kc * 64;
    __shared__ float cc[8][64];
    for (int i = threadIdx.x; i < 8 * 64; i += 128) {
        int r = i >> 6, col = i & 63;
        cc[r][col] = ctx[(size_t)(b * TT + t0 + r) * H2 + k0 + col];
    }
    __syncthreads();
    float acc[8] = {};
#pragma unroll 4
    for (int k = 0; k < 64; k++) {
        float w = Wc[(size_t)(k0 + k) * HH + h];
#pragma unroll
        for (int i = 0; i < 8; i++) acc[i] = fmaf(cc[i][k], w, acc[i]);
    }
#pragma unroll
    for (int i = 0; i < 8; i++)
        atomicAdd(&out_hid[(size_t)(b * TT + t0 + i) * HH + h], acc[i]);
}

// ---------------------------------------------------------------------------
extern "C" void kernel_launch(void* const* d_in, const int* in_sizes, int n_in,
                              void* d_out, int out_size) {
    const float* query  = (const float*)d_in[0];
    const float* states = (const float*)d_in[1];
    const int*   mask   = (const int*)d_in[2];
    const float* Wq     = (const float*)d_in[3];
    const float* bq     = (const float*)d_in[4];
    const float* Ws     = (const float*)d_in[5];
    const float* v      = (const float*)d_in[6];
    const float* Wc     = (const float*)d_in[7];
    const float* bc     = (const float*)d_in[8];

    float* out_ctx = (float*)d_out;                  // (B,T,2H)
    float* out_hid = out_ctx + BB * TT * H2;         // (B,T,H)
    float* out_att = out_hid + BB * TT * HH;         // (B,S,T)

    static cudaStream_t s1 = nullptr, s2 = nullptr;
    static cudaEvent_t ef, e1, e2, e3;
    if (!s1) {
        cudaStreamCreateWithFlags(&s1, cudaStreamNonBlocking);
        cudaStreamCreateWithFlags(&s2, cudaStreamNonBlocking);
        cudaEventCreateWithFlags(&ef, cudaEventDisableTiming);
        cudaEventCreateWithFlags(&e1, cudaEventDisableTiming);
        cudaEventCreateWithFlags(&e2, cudaEventDisableTiming);
        cudaEventCreateWithFlags(&e3, cudaEventDisableTiming);
        cudaFuncSetAttribute(align_kernel,
                             cudaFuncAttributeMaxDynamicSharedMemorySize,
                             TT * H2 * sizeof(float));
        cudaFuncSetAttribute(sf_mma,
                             cudaFuncAttributeMaxDynamicSharedMemorySize,
                             SMEM_MMA);
    }

    // fork
    cudaEventRecord(ef, 0);
    cudaStreamWaitEvent(s1, ef, 0);
    cudaStreamWaitEvent(s2, ef, 0);

    prep_B<<<dim3(16, 16), 256, 0, s1>>>(Ws);
    cudaEventRecord(e1, s1);

    zero_kernel<<<48, 256, 0, s2>>>((float4*)out_ctx);  // ctx + hid
    qf_kernel<<<dim3(8, 4, 4), 128, 0, s2>>>(query, Wq, bq);
    cudaEventRecord(e2, s2);  // align only needs qf
    hid_q_kernel<<<dim3(4, 4, 32), 128, 0, s2>>>(query, Wc, bc, out_hid);
    cudaEventRecord(e3, s2);  // zero + hid_q done (gates ctx/hidden atomics)

    prep_A<<<1024, 256>>>(states);
    cudaStreamWaitEvent(0, e1, 0);  // prep_B done
    sf_mma<<<dim3(16, 16), 512, SMEM_MMA>>>();
    cudaStreamWaitEvent(0, e2, 0);  // qf done
    align_kernel<<<dim3(32, BB), 512, TT * H2 * sizeof(float)>>>(v);
    softmax_kernel<<<dim3(TT, BB), 256>>>(mask, out_att);
    cudaStreamWaitEvent(0, e3, 0);  // zero + hid_q done
    ctx_kernel<<<dim3(8, 32, 4), 128>>>(states, out_ctx);
    hidden_kernel<<<dim3(4, 4, 64), 128>>>(Wc, out_ctx, out_hid);
}